// round 1
// baseline (speedup 1.0000x reference)
#include <cuda_runtime.h>

// Problem constants
#define C_IN   32
#define HH     64
#define WW     64
#define OC     64
#define NIMG   512        // P*B
#define PP     4
#define BB     128
#define ROWS   8          // output rows per CTA
#define TILE_T 10         // ROWS + 2 halo
#define TILE_U 68         // 66 wrapped cols padded to 68 (keeps 16B alignment: 68*4=272=17*16)
#define KW     288        // C_IN * 9

// Scratch: per-(image, rowblock) pooled partial sums, reduced in kernel B.
__device__ float g_partial[NIMG * 8 * OC];   // 1 MB

// ---------------------------------------------------------------------------
// Kernel A: fused conv3x3(circular) + bias + ReLU + spatial-sum (per rowblock)
// Grid: (512 images, 8 rowblocks). 512 threads.
// Dynamic smem: x tile (32*10*68 f) + transposed weights (288*64 f) + pool(64)
// ---------------------------------------------------------------------------
__global__ __launch_bounds__(512, 1)
void conv_pool_kernel(const float* __restrict__ x,
                      const float* __restrict__ cw,
                      const float* __restrict__ cb) {
    extern __shared__ float smem[];
    float* x_s  = smem;                               // 21760 floats
    float* w_s  = smem + C_IN * TILE_T * TILE_U;      // 18432 floats, layout [k][oc]
    float* pool = w_s + KW * OC;                      // 64 floats

    const int n   = blockIdx.x;
    const int rb  = blockIdx.y;
    const int r0  = rb * ROWS;
    const int tid = threadIdx.x;

    // Load weights transposed: w_s[k*64 + oc] = cw[oc*288 + k]
    for (int i = tid; i < OC * KW; i += 512) {
        int oc = i / KW, k = i % KW;
        w_s[k * OC + oc] = cw[i];
    }

    // Load input tile with circular halo. Tile row t -> global row (r0+t-1)%64,
    // tile col u (0..65) -> global col (u-1)%64.
    const float* xn = x + (size_t)n * (C_IN * HH * WW);
    for (int i = tid; i < C_IN * TILE_T * 66; i += 512) {
        int row = i / 66, u = i % 66;
        int c = row / TILE_T, t = row % TILE_T;
        int gr = (r0 + t - 1 + HH) & (HH - 1);
        int gc = (u - 1 + WW) & (WW - 1);
        x_s[(c * TILE_T + t) * TILE_U + u] = xn[c * HH * WW + gr * WW + gc];
    }
    if (tid < OC) pool[tid] = 0.0f;
    __syncthreads();

    // Thread tiling: 16 col-groups x 8 oc-groups x 4 row-groups = 512 threads.
    const int colg = tid & 15;          // 4 cols each
    const int ocg  = (tid >> 4) & 7;    // 8 ocs each
    const int rowg = tid >> 7;          // 0..3
    const int c0   = colg * 4;
    const int oc0  = ocg * 8;

    float bias[8];
#pragma unroll
    for (int o = 0; o < 8; o++) bias[o] = __ldg(&cb[oc0 + o]);

    float osum[8];
#pragma unroll
    for (int o = 0; o < 8; o++) osum[o] = 0.0f;

    for (int rr = 0; rr < 2; rr++) {
        const int row = rr * 4 + rowg;   // output row 0..7
        float acc[8][4];
#pragma unroll
        for (int o = 0; o < 8; o++)
#pragma unroll
            for (int cc = 0; cc < 4; cc++) acc[o][cc] = 0.0f;

        for (int ic = 0; ic < C_IN; ic++) {
#pragma unroll
            for (int dy = 0; dy < 3; dy++) {
                const float* xr = &x_s[(ic * TILE_T + row + dy) * TILE_U + c0];
                float4 a4 = *(const float4*)xr;
                float xv[6];
                xv[0] = a4.x; xv[1] = a4.y; xv[2] = a4.z; xv[3] = a4.w;
                xv[4] = xr[4]; xv[5] = xr[5];
                const float* wk = &w_s[(ic * 9 + dy * 3) * OC + oc0];
#pragma unroll
                for (int dx = 0; dx < 3; dx++) {
                    float4 w0 = *(const float4*)(wk + dx * OC);
                    float4 w1 = *(const float4*)(wk + dx * OC + 4);
                    float wv[8];
                    wv[0] = w0.x; wv[1] = w0.y; wv[2] = w0.z; wv[3] = w0.w;
                    wv[4] = w1.x; wv[5] = w1.y; wv[6] = w1.z; wv[7] = w1.w;
#pragma unroll
                    for (int o = 0; o < 8; o++)
#pragma unroll
                        for (int cc = 0; cc < 4; cc++)
                            acc[o][cc] = fmaf(wv[o], xv[dx + cc], acc[o][cc]);
                }
            }
        }
        // bias + ReLU + accumulate into per-thread pooled sums
#pragma unroll
        for (int o = 0; o < 8; o++)
#pragma unroll
            for (int cc = 0; cc < 4; cc++)
                osum[o] += fmaxf(acc[o][cc] + bias[o], 0.0f);
    }

#pragma unroll
    for (int o = 0; o < 8; o++) atomicAdd(&pool[oc0 + o], osum[o]);
    __syncthreads();

    if (tid < OC) g_partial[(n * 8 + rb) * OC + tid] = pool[tid];
}

// ---------------------------------------------------------------------------
// Kernel B: node reduce -> edge MLP (16 edges) -> mean over send -> out MLP.
// Grid: 128 (one CTA per batch element b). 256 threads.
// ---------------------------------------------------------------------------
__global__ __launch_bounds__(256, 1)
void mlp_kernel(const float* __restrict__ ew1, const float* __restrict__ eb1,
                const float* __restrict__ ew2, const float* __restrict__ eb2,
                const float* __restrict__ ow1, const float* __restrict__ ob1,
                const float* __restrict__ ow2, const float* __restrict__ ob2,
                float* __restrict__ out) {
    extern __shared__ float s[];
    float* sw1  = s;              // 128*64 = 8192
    float* sw2  = sw1 + 8192;     // 64*64  = 4096
    float* so1  = sw2 + 4096;     // 64*64  = 4096
    float* so2  = so1 + 4096;     // 64
    float* sb1  = so2 + 64;       // 64
    float* sb2  = sb1 + 64;       // 64
    float* sb3  = sb2 + 64;       // 64
    float* node = sb3 + 64;       // 4*64
    float* h1s  = node + 256;     // 16*64
    float* h2s  = h1s + 1024;     // 16*64
    float* msg  = h2s + 1024;     // 4*64
    float* o1s  = msg + 256;      // 4*64

    const int b = blockIdx.x;
    const int tid = threadIdx.x;

    for (int i = tid; i < 8192; i += 256) sw1[i] = ew1[i];
    for (int i = tid; i < 4096; i += 256) sw2[i] = ew2[i];
    for (int i = tid; i < 4096; i += 256) so1[i] = ow1[i];
    if (tid < 64) {
        so2[tid] = ow2[tid];
        sb1[tid] = eb1[tid];
        sb2[tid] = eb2[tid];
        sb3[tid] = ob1[tid];
    }

    // nodes[p][h]: mean over 8 rowblock partials / (64*64)
    const int p = tid >> 6;
    const int h = tid & 63;
    {
        float sum = 0.0f;
        const float* gp = &g_partial[(p * BB + b) * 8 * OC + h];
#pragma unroll
        for (int k = 0; k < 8; k++) sum += gp[k * OC];
        node[p * OC + h] = sum * (1.0f / 4096.0f);
    }
    __syncthreads();

    // h1[e][h] = relu(b1 + send_i . W1[0:64] + recv_j . W1[64:128])
    for (int e4 = 0; e4 < 4; e4++) {
        int e = e4 * 4 + p;            // 16 edges
        int i = e >> 2, j = e & 3;
        float s1 = sb1[h];
        for (int k = 0; k < 64; k++) {
            s1 = fmaf(node[i * 64 + k], sw1[k * 64 + h], s1);
            s1 = fmaf(node[j * 64 + k], sw1[(64 + k) * 64 + h], s1);
        }
        h1s[e * 64 + h] = fmaxf(s1, 0.0f);
    }
    __syncthreads();

    // h2[e][h] = relu(b2 + h1[e] . W2)
    for (int e4 = 0; e4 < 4; e4++) {
        int e = e4 * 4 + p;
        float s2 = sb2[h];
        for (int k = 0; k < 64; k++)
            s2 = fmaf(h1s[e * 64 + k], sw2[k * 64 + h], s2);
        h2s[e * 64 + h] = fmaxf(s2, 0.0f);
    }
    __syncthreads();

    // msg[j][h] = mean over send i of h2[(i,j)][h]
    {
        int j = p;
        float m = 0.25f * (h2s[(0 * 4 + j) * 64 + h] + h2s[(1 * 4 + j) * 64 + h] +
                           h2s[(2 * 4 + j) * 64 + h] + h2s[(3 * 4 + j) * 64 + h]);
        msg[j * 64 + h] = m;
    }
    __syncthreads();

    // o1[j][h] = relu(ob1 + msg[j] . o_w1)
    {
        int j = p;
        float s3 = sb3[h];
        for (int k = 0; k < 64; k++)
            s3 = fmaf(msg[j * 64 + k], so1[k * 64 + h], s3);
        o1s[j * 64 + h] = fmaxf(s3, 0.0f);
    }
    __syncthreads();

    // out[b][j] = ob2 + o1[j] . o_w2
    if (tid < 4) {
        float s4 = __ldg(&ob2[0]);
        for (int k = 0; k < 64; k++)
            s4 = fmaf(o1s[tid * 64 + k], so2[k], s4);
        out[b * PP + tid] = s4;
    }
}

// ---------------------------------------------------------------------------
extern "C" void kernel_launch(void* const* d_in, const int* in_sizes, int n_in,
                              void* d_out, int out_size) {
    const float* x      = (const float*)d_in[0];
    const float* conv_w = (const float*)d_in[1];
    const float* conv_b = (const float*)d_in[2];
    const float* e_w1   = (const float*)d_in[3];
    const float* e_b1   = (const float*)d_in[4];
    const float* e_w2   = (const float*)d_in[5];
    const float* e_b2   = (const float*)d_in[6];
    const float* o_w1   = (const float*)d_in[7];
    const float* o_b1   = (const float*)d_in[8];
    const float* o_w2   = (const float*)d_in[9];
    const float* o_b2   = (const float*)d_in[10];
    float* out = (float*)d_out;

    const int smemA = (C_IN * TILE_T * TILE_U + KW * OC + 64) * (int)sizeof(float);
    const int smemB = (8192 + 4096 + 4096 + 64 * 4 + 256 + 1024 + 1024 + 256 + 256) *
                      (int)sizeof(float);

    cudaFuncSetAttribute(conv_pool_kernel,
                         cudaFuncAttributeMaxDynamicSharedMemorySize, smemA);
    cudaFuncSetAttribute(mlp_kernel,
                         cudaFuncAttributeMaxDynamicSharedMemorySize, smemB);

    dim3 gridA(NIMG, 8);
    conv_pool_kernel<<<gridA, 512, smemA>>>(x, conv_w, conv_b);
    mlp_kernel<<<BB, 256, smemB>>>(e_w1, e_b1, e_w2, e_b2,
                                   o_w1, o_b1, o_w2, o_b2, out);
}

// round 3
// speedup vs baseline: 3.0866x; 3.0866x over previous
#include <cuda_runtime.h>
#include <cuda_bf16.h>
#include <cstdint>

// ---------------------------------------------------------------- constants
#define HH     64
#define WW     64
#define CIN    32
#define OCN    64
#define NIMG   512
#define NTILE  16384          // 512 images * 32 row-pairs (128 pixels each)
#define GRIDC  148
#define PP     4
#define BB     128

#define LDK    296            // padded K stride (elements): 288 + 8
#define LDKB   592            // bytes
#define ST_IC  40             // staging ic-slot (bf16): 80 bytes/col, 16B aligned

// SMEM layout (bytes)
#define SM_BIAS   0           // 64 f32  (256 B)
#define SM_POOL   256         // 256 f32 (1024 B)
#define ST_OFF    1280        // staging 4*66*40 bf16 = 21120 -> ends 22400
#define A_OFF     22400       // 128 * 592 = 75776 -> ends 98176
#define B_OFF     98176       // 64 * 592  = 37888 -> ends 136064
#define SMEM_BYTES 136064

__device__ __align__(16) __nv_bfloat16 g_wt[OCN * 288];   // tap-major weights
__device__ float g_partial[NTILE * OCN];                  // per-tile pooled sums

// ---------------------------------------------------------------- helpers
__device__ __forceinline__ uint32_t smem_u32(const void* p) {
    uint32_t a;
    asm("{ .reg .u64 t; cvta.to.shared.u64 t, %1; cvt.u32.u64 %0, t; }"
        : "=r"(a) : "l"(p));
    return a;
}

__device__ __forceinline__ void ldsm_x4(uint32_t& r0, uint32_t& r1,
                                        uint32_t& r2, uint32_t& r3,
                                        uint32_t addr) {
    asm volatile("ldmatrix.sync.aligned.m8n8.x4.shared.b16 {%0,%1,%2,%3}, [%4];"
                 : "=r"(r0), "=r"(r1), "=r"(r2), "=r"(r3) : "r"(addr));
}

__device__ __forceinline__ void mma16816(float* c,
                                         uint32_t a0, uint32_t a1, uint32_t a2, uint32_t a3,
                                         uint32_t b0, uint32_t b1) {
    asm volatile(
        "mma.sync.aligned.m16n8k16.row.col.f32.bf16.bf16.f32 "
        "{%0,%1,%2,%3}, {%4,%5,%6,%7}, {%8,%9}, {%0,%1,%2,%3};"
        : "+f"(c[0]), "+f"(c[1]), "+f"(c[2]), "+f"(c[3])
        : "r"(a0), "r"(a1), "r"(a2), "r"(a3), "r"(b0), "r"(b1));
}

__device__ __forceinline__ uint32_t pack_bf16x2(float a, float b) {
    __nv_bfloat162 h = __floats2bfloat162_rn(a, b);   // x=a (low), y=b (high)
    return *(uint32_t*)&h;
}

// ---------------------------------------------------------------- weight reorder
// g_wt[oc][tap*32 + ic] = bf16(cw[oc][ic][tap]) ; tap = dy*3+dx
__global__ void wt_reorder_kernel(const float* __restrict__ cw) {
    int oc = blockIdx.x;
    for (int i = threadIdx.x; i < 288; i += blockDim.x) {
        int ic = i / 9, tap = i % 9;
        g_wt[oc * 288 + tap * 32 + ic] = __float2bfloat16(cw[oc * 288 + i]);
    }
}

// ---------------------------------------------------------------- conv (HMMA)
__global__ __launch_bounds__(256, 1)
void conv_mma_kernel(const float* __restrict__ x, const float* __restrict__ cb) {
    extern __shared__ char smem[];
    const uint32_t sbase = smem_u32(smem);
    const int tid  = threadIdx.x;
    const int wid  = tid >> 5;
    const int lane = tid & 31;

    float* sbias = (float*)(smem + SM_BIAS);
    float* spool = (float*)(smem + SM_POOL);
    __nv_bfloat16* st = (__nv_bfloat16*)(smem + ST_OFF);

    if (tid < OCN) sbias[tid] = cb[tid];

    // Build B once: copy g_wt rows (576 B) into stride-592 rows. 64*36 uint4 tasks.
    for (int i = tid; i < OCN * 36; i += 256) {
        int oc = i / 36, u = i % 36;
        *(uint4*)(smem + B_OFF + oc * LDKB + u * 16) =
            *(const uint4*)((const char*)g_wt + oc * 576 + u * 16);
    }
    __syncthreads();

    // Per-warp geometry
    const int wm = wid & 3;             // pixel group (32 pixels)
    const int wn = wid >> 2;            // oc group (32 ocs)
    const uint32_t aBase = sbase + A_OFF + (wm * 32 + (lane & 15)) * LDKB + (lane >> 4) * 16;
    const uint32_t bBase = sbase + B_OFF +
        (wn * 32 + ((lane & 7) | ((lane & 16) >> 1))) * LDKB + ((lane >> 3) & 1) * 16;

    // Per-thread bias values (fixed oc mapping)
    float bvals[8];
#pragma unroll
    for (int nt = 0; nt < 4; nt++)
#pragma unroll
        for (int c = 0; c < 2; c++)
            bvals[nt * 2 + c] = sbias[wn * 32 + nt * 8 + (lane & 3) * 2 + c];

    const int icp  = tid >> 4;          // 0..15 (ic pair)
    const int colg = tid & 15;          // 0..15 (cols colg, colg+16, +32, +48)

    for (int t = blockIdx.x; t < NTILE; t += GRIDC) {
        const int n  = t >> 5;
        const int r0 = (t & 31) * 2;
        const float* xn = x + (size_t)n * (CIN * HH * WW);

        // ---- staging: st[(row*66+col)*40 + ic] bf16, halo cols 0 and 65.
        {
            const float* b0 = xn + (2 * icp) * (HH * WW);
            const float* b1 = b0 + HH * WW;
#pragma unroll
            for (int r = 0; r < 4; r++) {
                int gr = (r0 + r - 1) & (HH - 1);
                const float* p0 = b0 + gr * WW;
                const float* p1 = b1 + gr * WW;
#pragma unroll
                for (int j = 0; j < 4; j++) {
                    int c = colg + 16 * j;
                    *(uint32_t*)((char*)st + ((r * 66 + c + 1) * ST_IC + 2 * icp) * 2) =
                        pack_bf16x2(p0[c], p1[c]);
                }
                if (colg == 0)
                    *(uint32_t*)((char*)st + ((r * 66 + 0) * ST_IC + 2 * icp) * 2) =
                        pack_bf16x2(p0[63], p1[63]);
                if (colg == 15)
                    *(uint32_t*)((char*)st + ((r * 66 + 65) * ST_IC + 2 * icp) * 2) =
                        pack_bf16x2(p0[0], p1[0]);
            }
        }
        __syncthreads();

        // ---- im2col A build: (pix, tap) -> 64B contiguous copy
        for (int task = tid; task < 128 * 9; task += 256) {
            int pix = task / 9, tap = task - pix * 9;
            int pr = pix >> 6, pc = pix & 63;
            int dy = tap / 3, dx = tap - dy * 3;
            const uint4* src =
                (const uint4*)((char*)st + ((pr + dy) * 66 + pc + dx) * (ST_IC * 2));
            uint4* dst = (uint4*)(smem + A_OFF + pix * LDKB + tap * 64);
            dst[0] = src[0]; dst[1] = src[1]; dst[2] = src[2]; dst[3] = src[3];
        }
        __syncthreads();

        // ---- 18 k-steps of m16n8k16 HMMA
        float acc[2][4][4];
#pragma unroll
        for (int mt = 0; mt < 2; mt++)
#pragma unroll
            for (int nt = 0; nt < 4; nt++)
#pragma unroll
                for (int e = 0; e < 4; e++) acc[mt][nt][e] = 0.0f;

#pragma unroll
        for (int kk = 0; kk < 18; kk++) {
            uint32_t a[2][4], b[2][4];
#pragma unroll
            for (int mt = 0; mt < 2; mt++)
                ldsm_x4(a[mt][0], a[mt][1], a[mt][2], a[mt][3],
                        aBase + mt * 16 * LDKB + kk * 32);
#pragma unroll
            for (int g = 0; g < 2; g++)
                ldsm_x4(b[g][0], b[g][1], b[g][2], b[g][3],
                        bBase + g * 16 * LDKB + kk * 32);
#pragma unroll
            for (int mt = 0; mt < 2; mt++) {
                mma16816(acc[mt][0], a[mt][0], a[mt][1], a[mt][2], a[mt][3], b[0][0], b[0][1]);
                mma16816(acc[mt][1], a[mt][0], a[mt][1], a[mt][2], a[mt][3], b[0][2], b[0][3]);
                mma16816(acc[mt][2], a[mt][0], a[mt][1], a[mt][2], a[mt][3], b[1][0], b[1][1]);
                mma16816(acc[mt][3], a[mt][0], a[mt][1], a[mt][2], a[mt][3], b[1][2], b[1][3]);
            }
        }

        // ---- epilogue: bias + ReLU + pool, all in registers
        float ps[8];
#pragma unroll
        for (int i = 0; i < 8; i++) ps[i] = 0.0f;
#pragma unroll
        for (int mt = 0; mt < 2; mt++)
#pragma unroll
            for (int nt = 0; nt < 4; nt++)
#pragma unroll
                for (int h = 0; h < 2; h++) {
                    ps[nt * 2 + 0] += fmaxf(acc[mt][nt][2 * h + 0] + bvals[nt * 2 + 0], 0.0f);
                    ps[nt * 2 + 1] += fmaxf(acc[mt][nt][2 * h + 1] + bvals[nt * 2 + 1], 0.0f);
                }
        // reduce over the 8 pixel-rows (lane bits 2..4)
#pragma unroll
        for (int off = 4; off < 32; off <<= 1)
#pragma unroll
            for (int i = 0; i < 8; i++)
                ps[i] += __shfl_xor_sync(0xFFFFFFFFu, ps[i], off);

        if (lane < 4) {
#pragma unroll
            for (int nt = 0; nt < 4; nt++) {
                spool[wm * 64 + wn * 32 + nt * 8 + lane * 2 + 0] = ps[nt * 2 + 0];
                spool[wm * 64 + wn * 32 + nt * 8 + lane * 2 + 1] = ps[nt * 2 + 1];
            }
        }
        __syncthreads();

        if (tid < OCN)
            g_partial[(size_t)t * OCN + tid] =
                spool[tid] + spool[64 + tid] + spool[128 + tid] + spool[192 + tid];
        // (no extra sync needed: next writes to spool occur only after the next
        //  two __syncthreads barriers, which tid<64 must also pass)
    }
}

// ---------------------------------------------------------------- graph MLP
__global__ __launch_bounds__(256, 1)
void mlp_kernel(const float* __restrict__ ew1, const float* __restrict__ eb1,
                const float* __restrict__ ew2, const float* __restrict__ eb2,
                const float* __restrict__ ow1, const float* __restrict__ ob1,
                const float* __restrict__ ow2, const float* __restrict__ ob2,
                float* __restrict__ out) {
    extern __shared__ float s[];
    float* sw1  = s;              // 128*64
    float* sw2  = sw1 + 8192;     // 64*64
    float* so1  = sw2 + 4096;     // 64*64
    float* so2  = so1 + 4096;     // 64
    float* sb1  = so2 + 64;       // 64
    float* sb2  = sb1 + 64;       // 64
    float* sb3  = sb2 + 64;       // 64
    float* node = sb3 + 64;       // 4*64
    float* us   = node + 256;     // 4*64
    float* vs   = us + 256;       // 4*64
    float* h1s  = vs + 256;       // 16*64
    float* h2s  = h1s + 1024;     // 16*64
    float* msg  = h2s + 1024;     // 4*64
    float* o1s  = msg + 256;      // 4*64

    const int b = blockIdx.x;
    const int tid = threadIdx.x;
    const int p = tid >> 6;
    const int h = tid & 63;

    for (int i = tid; i < 8192; i += 256) sw1[i] = ew1[i];
    for (int i = tid; i < 4096; i += 256) sw2[i] = ew2[i];
    for (int i = tid; i < 4096; i += 256) so1[i] = ow1[i];
    if (tid < 64) {
        so2[tid] = ow2[tid];
        sb1[tid] = eb1[tid];
        sb2[tid] = eb2[tid];
        sb3[tid] = ob1[tid];
    }

    // nodes[p][h] = mean over 32 tile partials / 4096
    {
        const float* gp = &g_partial[(size_t)((p * BB + b) * 32) * OCN + h];
        float sum = 0.0f;
#pragma unroll
        for (int k = 0; k < 32; k++) sum += gp[k * OCN];
        node[p * 64 + h] = sum * (1.0f / 4096.0f);
    }
    __syncthreads();

    // u/v factorization of edge layer 1: h1[(i,j)] = relu(u_i + v_j + b1)
    {
        float uu = 0.0f, vv = 0.0f;
        for (int k = 0; k < 64; k++) {
            float nk = node[p * 64 + k];
            uu = fmaf(nk, sw1[k * 64 + h], uu);
            vv = fmaf(nk, sw1[(64 + k) * 64 + h], vv);
        }
        us[p * 64 + h] = uu;
        vs[p * 64 + h] = vv;
    }
    __syncthreads();

#pragma unroll
    for (int e4 = 0; e4 < 4; e4++) {  // edge e = e4*4+p : i=e4, j=p
        h1s[(e4 * 4 + p) * 64 + h] =
            fmaxf(us[e4 * 64 + h] + vs[p * 64 + h] + sb1[h], 0.0f);
    }
    __syncthreads();

    // h2[e] = relu(b2 + h1[e] . W2)
    {
        float acc[4];
#pragma unroll
        for (int e4 = 0; e4 < 4; e4++) acc[e4] = sb2[h];
        for (int k = 0; k < 64; k++) {
            float w = sw2[k * 64 + h];
#pragma unroll
            for (int e4 = 0; e4 < 4; e4++)
                acc[e4] = fmaf(h1s[(e4 * 4 + p) * 64 + k], w, acc[e4]);
        }
#pragma unroll
        for (int e4 = 0; e4 < 4; e4++)
            h2s[(e4 * 4 + p) * 64 + h] = fmaxf(acc[e4], 0.0f);
    }
    __syncthreads();

    // msg[j] = mean over send i ; then o1 = relu(msg . o_w1 + ob1)
    {
        float m = 0.25f * (h2s[(0 * 4 + p) * 64 + h] + h2s[(1 * 4 + p) * 64 + h] +
                           h2s[(2 * 4 + p) * 64 + h] + h2s[(3 * 4 + p) * 64 + h]);
        msg[p * 64 + h] = m;
    }
    __syncthreads();
    {
        float s3 = sb3[h];
        for (int k = 0; k < 64; k++)
            s3 = fmaf(msg[p * 64 + k], so1[k * 64 + h], s3);
        o1s[p * 64 + h] = fmaxf(s3, 0.0f);
    }
    __syncthreads();

    if (tid < PP) {
        float s4 = __ldg(&ob2[0]);
        for (int k = 0; k < 64; k++)
            s4 = fmaf(o1s[tid * 64 + k], so2[k], s4);
        out[b * PP + tid] = s4;
    }
}

// ---------------------------------------------------------------- launch
extern "C" void kernel_launch(void* const* d_in, const int* in_sizes, int n_in,
                              void* d_out, int out_size) {
    const float* x      = (const float*)d_in[0];
    const float* conv_w = (const float*)d_in[1];
    const float* conv_b = (const float*)d_in[2];
    const float* e_w1   = (const float*)d_in[3];
    const float* e_b1   = (const float*)d_in[4];
    const float* e_w2   = (const float*)d_in[5];
    const float* e_b2   = (const float*)d_in[6];
    const float* o_w1   = (const float*)d_in[7];
    const float* o_b1   = (const float*)d_in[8];
    const float* o_w2   = (const float*)d_in[9];
    const float* o_b2   = (const float*)d_in[10];
    float* out = (float*)d_out;

    cudaFuncSetAttribute(conv_mma_kernel,
                         cudaFuncAttributeMaxDynamicSharedMemorySize, SMEM_BYTES);
    const int smemB = (8192 + 4096 + 4096 + 64 * 4 + 256 * 3 + 1024 * 2 + 256 * 2) *
                      (int)sizeof(float);
    cudaFuncSetAttribute(mlp_kernel,
                         cudaFuncAttributeMaxDynamicSharedMemorySize, smemB);

    wt_reorder_kernel<<<OCN, 256>>>(conv_w);
    conv_mma_kernel<<<GRIDC, 256, SMEM_BYTES>>>(x, conv_b);
    mlp_kernel<<<BB, 256, smemB>>>(e_w1, e_b1, e_w2, e_b2,
                                   o_w1, o_b1, o_w2, o_b2, out);
}

// round 5
// speedup vs baseline: 6.1598x; 1.9956x over previous
#include <cuda_runtime.h>
#include <cuda_bf16.h>
#include <cstdint>

// ---------------------------------------------------------------- constants
#define HH     64
#define WW     64
#define CIN    32
#define OCN    64
#define NIMG   512
#define NTILE  16384          // 512 images * 32 row-pairs (128 pixels each)
#define GRIDC  296            // 2 CTAs per SM
#define PP     4
#define BB     128
#define BPB    4              // batch elems per MLP CTA

#define LDK    296            // B tile padded K stride (elements)
#define LDKB   592            // bytes
#define ST_COL 80             // bytes per (row,col) slot (32 bf16 data + 16B pad)
#define ST_ROW (66 * ST_COL)  // 5280 bytes per staging row

// SMEM layout (bytes)
#define SM_BIAS   0           // 64 f32  (256 B)
#define SM_POOL   256         // 256 f32 (1024 B)
#define ST_OFF    1280        // staging 4*66*80 = 21120 -> ends 22400
#define B_OFF     22400       // 64 * 592 = 37888 -> ends 60288
#define SMEM_BYTES 60288

__device__ float g_partial[NTILE * OCN];                  // per-tile pooled sums

// ---------------------------------------------------------------- helpers
__device__ __forceinline__ uint32_t smem_u32(const void* p) {
    uint32_t a;
    asm("{ .reg .u64 t; cvta.to.shared.u64 t, %1; cvt.u32.u64 %0, t; }"
        : "=r"(a) : "l"(p));
    return a;
}

__device__ __forceinline__ void ldsm_x4(uint32_t& r0, uint32_t& r1,
                                        uint32_t& r2, uint32_t& r3,
                                        uint32_t addr) {
    asm volatile("ldmatrix.sync.aligned.m8n8.x4.shared.b16 {%0,%1,%2,%3}, [%4];"
                 : "=r"(r0), "=r"(r1), "=r"(r2), "=r"(r3) : "r"(addr));
}

__device__ __forceinline__ void mma16816(float* c,
                                         uint32_t a0, uint32_t a1, uint32_t a2, uint32_t a3,
                                         uint32_t b0, uint32_t b1) {
    asm volatile(
        "mma.sync.aligned.m16n8k16.row.col.f32.bf16.bf16.f32 "
        "{%0,%1,%2,%3}, {%4,%5,%6,%7}, {%8,%9}, {%0,%1,%2,%3};"
        : "+f"(c[0]), "+f"(c[1]), "+f"(c[2]), "+f"(c[3])
        : "r"(a0), "r"(a1), "r"(a2), "r"(a3), "r"(b0), "r"(b1));
}

__device__ __forceinline__ uint32_t pack_bf16x2(float a, float b) {
    __nv_bfloat162 h = __floats2bfloat162_rn(a, b);
    return *(uint32_t*)&h;
}

// ---------------------------------------------------------------- conv (HMMA)
__global__ __launch_bounds__(256, 2)
void conv_mma_kernel(const float* __restrict__ x, const float* __restrict__ cw,
                     const float* __restrict__ cb) {
    extern __shared__ char smem[];
    const uint32_t sbase = smem_u32(smem);
    const int tid  = threadIdx.x;
    const int wid  = tid >> 5;
    const int lane = tid & 31;

    float* sbias = (float*)(smem + SM_BIAS);
    float* spool = (float*)(smem + SM_POOL);
    char*  st    = smem + ST_OFF;

    if (tid < OCN) sbias[tid] = cb[tid];

    // Build B in-place from conv_w: B[oc][tap*32+ic] = bf16(cw[oc][ic][tap])
    {
        __nv_bfloat16* bw = (__nv_bfloat16*)(smem + B_OFF);
        for (int i = tid; i < OCN * 288; i += 256) {
            int oc = i / 288, k = i - oc * 288;
            int tap = k >> 5, ic = k & 31;
            bw[oc * LDK + k] = __float2bfloat16(cw[oc * 288 + ic * 9 + tap]);
        }
    }
    __syncthreads();

    // Per-warp geometry (fragment mapping identical to the R3-passing kernel)
    const int wm = wid & 3;             // pixel group (32 pixels)
    const int wn = wid >> 2;            // oc group (32 ocs)
    const uint32_t bBase = sbase + B_OFF +
        (wn * 32 + ((lane & 7) | ((lane & 16) >> 1))) * LDKB + ((lane >> 3) & 1) * 16;

    // A read directly from staging. Per-lane u = 2*kk + h16 selects the 8-elem
    // k-group; tap = u>>2 picks the (dy,dx) slot, sub = u&3 the 16B within it.
    // NOTE: h16 is folded into u ONLY — stA must NOT add (lane>>4)*16 (R4 bug).
    uint32_t stA[2];
#pragma unroll
    for (int mt = 0; mt < 2; mt++) {
        int pix = wm * 32 + mt * 16 + (lane & 15);
        int pr = pix >> 6, pc = pix & 63;
        stA[mt] = sbase + ST_OFF + pr * ST_ROW + pc * ST_COL;
    }

    float bvals[8];
#pragma unroll
    for (int nt = 0; nt < 4; nt++)
#pragma unroll
        for (int c = 0; c < 2; c++)
            bvals[nt * 2 + c] = sbias[wn * 32 + nt * 8 + (lane & 3) * 2 + c];

    const int icp  = tid >> 4;          // 0..15 (ic pair)
    const int colg = tid & 15;          // 0..15

    for (int t = blockIdx.x; t < NTILE; t += GRIDC) {
        const int n  = t >> 5;
        const int r0 = (t & 31) * 2;
        const float* xn = x + (size_t)n * (CIN * HH * WW);

        // ---- staging: st[(row*66+col)*ST_COL + 4*icp] bf16x2, halo cols 0/65
        {
            const float* c0 = xn + (2 * icp) * (HH * WW);
            const float* c1 = c0 + HH * WW;
#pragma unroll
            for (int r = 0; r < 4; r++) {
                int gr = (r0 + r - 1) & (HH - 1);
                const float* p0 = c0 + gr * WW;
                const float* p1 = c1 + gr * WW;
#pragma unroll
                for (int j = 0; j < 4; j++) {
                    int c = colg + 16 * j;
                    *(uint32_t*)(st + (r * 66 + c + 1) * ST_COL + 4 * icp) =
                        pack_bf16x2(p0[c], p1[c]);
                }
                if (colg == 0)
                    *(uint32_t*)(st + (r * 66 + 0) * ST_COL + 4 * icp) =
                        pack_bf16x2(p0[63], p1[63]);
                if (colg == 15)
                    *(uint32_t*)(st + (r * 66 + 65) * ST_COL + 4 * icp) =
                        pack_bf16x2(p0[0], p1[0]);
            }
        }
        __syncthreads();

        // ---- 18 k-steps of m16n8k16 HMMA, A read directly from staging
        float acc[2][4][4];
#pragma unroll
        for (int mt = 0; mt < 2; mt++)
#pragma unroll
            for (int nt = 0; nt < 4; nt++)
#pragma unroll
                for (int e = 0; e < 4; e++) acc[mt][nt][e] = 0.0f;

        const int h16 = (lane >> 4);
#pragma unroll
        for (int kk = 0; kk < 18; kk++) {
            const int u   = 2 * kk + h16;        // per-lane k-group index
            const int tap = u >> 2;              // warp-uniform (2kk,2kk+1 same tap)
            const int sub = u & 3;
            const int dy  = tap / 3, dx = tap - dy * 3;
            const uint32_t aoff = (uint32_t)(dy * ST_ROW + dx * ST_COL + sub * 16);

            uint32_t a[2][4], b[2][4];
#pragma unroll
            for (int mt = 0; mt < 2; mt++)
                ldsm_x4(a[mt][0], a[mt][1], a[mt][2], a[mt][3], stA[mt] + aoff);
#pragma unroll
            for (int g = 0; g < 2; g++)
                ldsm_x4(b[g][0], b[g][1], b[g][2], b[g][3],
                        bBase + g * 16 * LDKB + kk * 32);
#pragma unroll
            for (int mt = 0; mt < 2; mt++) {
                mma16816(acc[mt][0], a[mt][0], a[mt][1], a[mt][2], a[mt][3], b[0][0], b[0][1]);
                mma16816(acc[mt][1], a[mt][0], a[mt][1], a[mt][2], a[mt][3], b[0][2], b[0][3]);
                mma16816(acc[mt][2], a[mt][0], a[mt][1], a[mt][2], a[mt][3], b[1][0], b[1][1]);
                mma16816(acc[mt][3], a[mt][0], a[mt][1], a[mt][2], a[mt][3], b[1][2], b[1][3]);
            }
        }

        // ---- epilogue: bias + ReLU + pool in registers, shfl-reduce
        float ps[8];
#pragma unroll
        for (int i = 0; i < 8; i++) ps[i] = 0.0f;
#pragma unroll
        for (int mt = 0; mt < 2; mt++)
#pragma unroll
            for (int nt = 0; nt < 4; nt++)
#pragma unroll
                for (int h = 0; h < 2; h++) {
                    ps[nt * 2 + 0] += fmaxf(acc[mt][nt][2 * h + 0] + bvals[nt * 2 + 0], 0.0f);
                    ps[nt * 2 + 1] += fmaxf(acc[mt][nt][2 * h + 1] + bvals[nt * 2 + 1], 0.0f);
                }
#pragma unroll
        for (int off = 4; off < 32; off <<= 1)
#pragma unroll
            for (int i = 0; i < 8; i++)
                ps[i] += __shfl_xor_sync(0xFFFFFFFFu, ps[i], off);

        if (lane < 4) {
#pragma unroll
            for (int nt = 0; nt < 4; nt++) {
                spool[wm * 64 + wn * 32 + nt * 8 + lane * 2 + 0] = ps[nt * 2 + 0];
                spool[wm * 64 + wn * 32 + nt * 8 + lane * 2 + 1] = ps[nt * 2 + 1];
            }
        }
        __syncthreads();

        if (tid < OCN)
            g_partial[(size_t)t * OCN + tid] =
                spool[tid] + spool[64 + tid] + spool[128 + tid] + spool[192 + tid];
        // safe: staging is a different buffer; spool rewritten only after the
        // next staging __syncthreads, which tid<64 passes after reading spool
    }
}

// ---------------------------------------------------------------- graph MLP
__global__ __launch_bounds__(256, 1)
void mlp_kernel(const float* __restrict__ ew1, const float* __restrict__ eb1,
                const float* __restrict__ ew2, const float* __restrict__ eb2,
                const float* __restrict__ ow1, const float* __restrict__ ob1,
                const float* __restrict__ ow2, const float* __restrict__ ob2,
                float* __restrict__ out) {
    extern __shared__ float s[];
    float* sw1  = s;              // 128*64
    float* sw2  = sw1 + 8192;     // 64*64
    float* so1  = sw2 + 4096;     // 64*64
    float* so2  = so1 + 4096;     // 64
    float* sb1  = so2 + 64;       // 64
    float* sb2  = sb1 + 64;       // 64
    float* sb3  = sb2 + 64;       // 64
    float* node = sb3 + 64;       // 4*64
    float* us   = node + 256;     // 4*64
    float* vs   = us + 256;       // 4*64
    float* h1s  = vs + 256;       // 16*64
    float* h2s  = h1s + 1024;     // 16*64
    float* msg  = h2s + 1024;     // 4*64
    float* o1s  = msg + 256;      // 4*64

    const int tid = threadIdx.x;
    const int p = tid >> 6;
    const int h = tid & 63;

    for (int i = tid; i < 8192; i += 256) sw1[i] = ew1[i];
    for (int i = tid; i < 4096; i += 256) sw2[i] = ew2[i];
    for (int i = tid; i < 4096; i += 256) so1[i] = ow1[i];
    if (tid < 64) {
        so2[tid] = ow2[tid];
        sb1[tid] = eb1[tid];
        sb2[tid] = eb2[tid];
        sb3[tid] = ob1[tid];
    }
    __syncthreads();

    for (int bb = 0; bb < BPB; bb++) {
        const int b = blockIdx.x * BPB + bb;

        // nodes[p][h] = mean over 32 tile partials / 4096
        {
            const float* gp = &g_partial[(size_t)((p * BB + b) * 32) * OCN + h];
            float sum = 0.0f;
#pragma unroll
            for (int k = 0; k < 32; k++) sum += gp[k * OCN];
            node[p * 64 + h] = sum * (1.0f / 4096.0f);
        }
        __syncthreads();

        // u/v factorization of edge layer 1
        {
            float uu = 0.0f, vv = 0.0f;
            for (int k = 0; k < 64; k++) {
                float nk = node[p * 64 + k];
                uu = fmaf(nk, sw1[k * 64 + h], uu);
                vv = fmaf(nk, sw1[(64 + k) * 64 + h], vv);
            }
            us[p * 64 + h] = uu;
            vs[p * 64 + h] = vv;
        }
        __syncthreads();

#pragma unroll
        for (int e4 = 0; e4 < 4; e4++)
            h1s[(e4 * 4 + p) * 64 + h] =
                fmaxf(us[e4 * 64 + h] + vs[p * 64 + h] + sb1[h], 0.0f);
        __syncthreads();

        // h2[e] = relu(b2 + h1[e] . W2)
        {
            float acc[4];
#pragma unroll
            for (int e4 = 0; e4 < 4; e4++) acc[e4] = sb2[h];
            for (int k = 0; k < 64; k++) {
                float w = sw2[k * 64 + h];
#pragma unroll
                for (int e4 = 0; e4 < 4; e4++)
                    acc[e4] = fmaf(h1s[(e4 * 4 + p) * 64 + k], w, acc[e4]);
            }
#pragma unroll
            for (int e4 = 0; e4 < 4; e4++)
                h2s[(e4 * 4 + p) * 64 + h] = fmaxf(acc[e4], 0.0f);
        }
        __syncthreads();

        {
            float m = 0.25f * (h2s[(0 * 4 + p) * 64 + h] + h2s[(1 * 4 + p) * 64 + h] +
                               h2s[(2 * 4 + p) * 64 + h] + h2s[(3 * 4 + p) * 64 + h]);
            msg[p * 64 + h] = m;
        }
        __syncthreads();
        {
            float s3 = sb3[h];
            for (int k = 0; k < 64; k++)
                s3 = fmaf(msg[p * 64 + k], so1[k * 64 + h], s3);
            o1s[p * 64 + h] = fmaxf(s3, 0.0f);
        }
        __syncthreads();

        if (tid < PP) {
            float s4 = __ldg(&ob2[0]);
            for (int k = 0; k < 64; k++)
                s4 = fmaf(o1s[tid * 64 + k], so2[k], s4);
            out[b * PP + tid] = s4;
        }
        __syncthreads();
    }
}

// ---------------------------------------------------------------- launch
extern "C" void kernel_launch(void* const* d_in, const int* in_sizes, int n_in,
                              void* d_out, int out_size) {
    const float* x      = (const float*)d_in[0];
    const float* conv_w = (const float*)d_in[1];
    const float* conv_b = (const float*)d_in[2];
    const float* e_w1   = (const float*)d_in[3];
    const float* e_b1   = (const float*)d_in[4];
    const float* e_w2   = (const float*)d_in[5];
    const float* e_b2   = (const float*)d_in[6];
    const float* o_w1   = (const float*)d_in[7];
    const float* o_b1   = (const float*)d_in[8];
    const float* o_w2   = (const float*)d_in[9];
    const float* o_b2   = (const float*)d_in[10];
    float* out = (float*)d_out;

    cudaFuncSetAttribute(conv_mma_kernel,
                         cudaFuncAttributeMaxDynamicSharedMemorySize, SMEM_BYTES);
    const int smemB = (8192 + 4096 + 4096 + 64 * 4 + 256 * 3 + 1024 * 2 + 256 * 2) *
                      (int)sizeof(float);
    cudaFuncSetAttribute(mlp_kernel,
                         cudaFuncAttributeMaxDynamicSharedMemorySize, smemB);

    conv_mma_kernel<<<GRIDC, 256, SMEM_BYTES>>>(x, conv_w, conv_b);
    mlp_kernel<<<BB / BPB, 256, smemB>>>(e_w1, e_b1, e_w2, e_b2,
                                         o_w1, o_b1, o_w2, o_b2, out);
}

// round 7
// speedup vs baseline: 7.4110x; 1.2031x over previous
#include <cuda_runtime.h>
#include <cuda_bf16.h>
#include <cstdint>

// ---------------------------------------------------------------- constants
#define HH     64
#define WW     64
#define CIN    32
#define OCN    64
#define NIMG   512
#define NTILE  16384          // 512 images * 32 row-pairs (128 pixels each)
#define GRIDC  296            // 2 CTAs per SM
#define PP     4
#define BB     128

#define LDK    296            // B tile padded K stride (elements)
#define LDKB   592            // bytes
#define ST_COL 80             // bytes per (row,col) slot (32 bf16 data + 16B pad)
#define ST_ROW (66 * ST_COL)  // 5280 bytes per staging row
#define ST_BYTES (4 * ST_ROW) // 21120 bytes per staging buffer

// SMEM layout (bytes)
#define SM_BIAS   0           // 64 f32  (256 B)
#define SM_POOL   256         // 256 f32 (1024 B)
#define ST_OFF    1280        // 2 staging buffers: 2*21120 -> ends 43520
#define B_OFF     43520       // 64 * 592 = 37888 -> ends 81408
#define SMEM_BYTES 81408

__device__ float g_partial[NTILE * OCN];                  // per-tile pooled sums

// ---------------------------------------------------------------- helpers
__device__ __forceinline__ uint32_t smem_u32(const void* p) {
    uint32_t a;
    asm("{ .reg .u64 t; cvta.to.shared.u64 t, %1; cvt.u32.u64 %0, t; }"
        : "=r"(a) : "l"(p));
    return a;
}

__device__ __forceinline__ void ldsm_x4(uint32_t& r0, uint32_t& r1,
                                        uint32_t& r2, uint32_t& r3,
                                        uint32_t addr) {
    asm volatile("ldmatrix.sync.aligned.m8n8.x4.shared.b16 {%0,%1,%2,%3}, [%4];"
                 : "=r"(r0), "=r"(r1), "=r"(r2), "=r"(r3) : "r"(addr));
}

__device__ __forceinline__ void mma16816(float* c,
                                         uint32_t a0, uint32_t a1, uint32_t a2, uint32_t a3,
                                         uint32_t b0, uint32_t b1) {
    asm volatile(
        "mma.sync.aligned.m16n8k16.row.col.f32.bf16.bf16.f32 "
        "{%0,%1,%2,%3}, {%4,%5,%6,%7}, {%8,%9}, {%0,%1,%2,%3};"
        : "+f"(c[0]), "+f"(c[1]), "+f"(c[2]), "+f"(c[3])
        : "r"(a0), "r"(a1), "r"(a2), "r"(a3), "r"(b0), "r"(b1));
}

__device__ __forceinline__ uint32_t pack_bf16x2(float a, float b) {
    __nv_bfloat162 h = __floats2bfloat162_rn(a, b);
    return *(uint32_t*)&h;
}

// ---------------------------------------------------------------- conv (HMMA)
__global__ __launch_bounds__(256, 2)
void conv_mma_kernel(const float* __restrict__ x, const float* __restrict__ cw,
                     const float* __restrict__ cb) {
    extern __shared__ char smem[];
    const uint32_t sbase = smem_u32(smem);
    const int tid  = threadIdx.x;
    const int wid  = tid >> 5;
    const int lane = tid & 31;

    float* sbias = (float*)(smem + SM_BIAS);
    float* spool = (float*)(smem + SM_POOL);

    if (tid < OCN) sbias[tid] = cb[tid];

    // Build B from conv_w: B[oc][tap*32+ic] = bf16(cw[oc][ic][tap])
    {
        __nv_bfloat16* bw = (__nv_bfloat16*)(smem + B_OFF);
        for (int i = tid; i < OCN * 288; i += 256) {
            int oc = i / 288, k = i - oc * 288;
            int tap = k >> 5, ic = k & 31;
            bw[oc * LDK + k] = __float2bfloat16(cw[oc * 288 + ic * 9 + tap]);
        }
    }

    // Per-warp geometry
    const int wm = wid & 3;             // pixel group (32 pixels)
    const int wn = wid >> 2;            // oc group (32 ocs)
    const uint32_t bBase = sbase + B_OFF +
        (wn * 32 + ((lane & 7) | ((lane & 16) >> 1))) * LDKB + ((lane >> 3) & 1) * 16;

    uint32_t stA[2];
#pragma unroll
    for (int mt = 0; mt < 2; mt++) {
        int pix = wm * 32 + mt * 16 + (lane & 15);
        int pr = pix >> 6, pc = pix & 63;
        stA[mt] = sbase + ST_OFF + pr * ST_ROW + pc * ST_COL;
    }

    float bvals[8];
#pragma unroll
    for (int nt = 0; nt < 4; nt++)
#pragma unroll
        for (int c = 0; c < 2; c++)
            bvals[nt * 2 + c] = sbias[wn * 32 + nt * 8 + (lane & 3) * 2 + c];

    const int icp  = tid >> 4;          // 0..15 (ic pair)
    const int colg = tid & 15;          // 0..15
    const bool isLo = (colg == 0);
    const bool isHi = (colg == 15);

    // Prefetch registers for one tile's staging data (raw fp32)
    float pv0[16], pv1[16];             // main cols
    float hv0[4],  hv1[4];              // halo (colg 0 or 15 only)

    // ---- load tile t's input into registers (LDGs; latency hidden by caller)
    auto load_regs = [&](int t) {
        const int n  = t >> 5;
        const int r0 = (t & 31) * 2;
        const float* xn = x + (size_t)n * (CIN * HH * WW);
        const float* c0 = xn + (2 * icp) * (HH * WW);
        const float* c1 = c0 + HH * WW;
#pragma unroll
        for (int r = 0; r < 4; r++) {
            int gr = (r0 + r - 1) & (HH - 1);
            const float* p0 = c0 + gr * WW;
            const float* p1 = c1 + gr * WW;
#pragma unroll
            for (int j = 0; j < 4; j++) {
                int c = colg + 16 * j;
                pv0[r * 4 + j] = p0[c];
                pv1[r * 4 + j] = p1[c];
            }
            if (isLo) { hv0[r] = p0[63]; hv1[r] = p1[63]; }
            if (isHi) { hv0[r] = p0[0];  hv1[r] = p1[0];  }
        }
    };

    // ---- convert + store registers into staging buffer `buf`
    auto store_regs = [&](int buf) {
        char* st = smem + ST_OFF + buf * ST_BYTES;
#pragma unroll
        for (int r = 0; r < 4; r++) {
#pragma unroll
            for (int j = 0; j < 4; j++) {
                int c = colg + 16 * j;
                *(uint32_t*)(st + (r * 66 + c + 1) * ST_COL + 4 * icp) =
                    pack_bf16x2(pv0[r * 4 + j], pv1[r * 4 + j]);
            }
            if (isLo)
                *(uint32_t*)(st + (r * 66 + 0) * ST_COL + 4 * icp) =
                    pack_bf16x2(hv0[r], hv1[r]);
            if (isHi)
                *(uint32_t*)(st + (r * 66 + 65) * ST_COL + 4 * icp) =
                    pack_bf16x2(hv0[r], hv1[r]);
        }
    };

    // ---- prime the pipeline
    int t0 = blockIdx.x;
    load_regs(t0);
    store_regs(0);
    __syncthreads();

    const int h16 = (lane >> 4);
    int it = 0;
    for (int t = t0; t < NTILE; t += GRIDC, it ^= 1) {
        const int tn = t + GRIDC;
        const bool havenext = (tn < NTILE);
        if (havenext) load_regs(tn);          // LDGs in flight during MMA

        // ---- 18 k-steps of m16n8k16 HMMA from staging buffer `it`
        const uint32_t bufoff = (uint32_t)(it * ST_BYTES);
        float acc[2][4][4];
#pragma unroll
        for (int mt = 0; mt < 2; mt++)
#pragma unroll
            for (int nt = 0; nt < 4; nt++)
#pragma unroll
                for (int e = 0; e < 4; e++) acc[mt][nt][e] = 0.0f;

#pragma unroll
        for (int kk = 0; kk < 18; kk++) {
            const int u   = 2 * kk + h16;
            const int tap = u >> 2;
            const int sub = u & 3;
            const int dy  = tap / 3, dx = tap - dy * 3;
            const uint32_t aoff = (uint32_t)(dy * ST_ROW + dx * ST_COL + sub * 16);

            uint32_t a[2][4], b[2][4];
#pragma unroll
            for (int mt = 0; mt < 2; mt++)
                ldsm_x4(a[mt][0], a[mt][1], a[mt][2], a[mt][3],
                        stA[mt] + bufoff + aoff);
#pragma unroll
            for (int g = 0; g < 2; g++)
                ldsm_x4(b[g][0], b[g][1], b[g][2], b[g][3],
                        bBase + g * 16 * LDKB + kk * 32);
#pragma unroll
            for (int mt = 0; mt < 2; mt++) {
                mma16816(acc[mt][0], a[mt][0], a[mt][1], a[mt][2], a[mt][3], b[0][0], b[0][1]);
                mma16816(acc[mt][1], a[mt][0], a[mt][1], a[mt][2], a[mt][3], b[0][2], b[0][3]);
                mma16816(acc[mt][2], a[mt][0], a[mt][1], a[mt][2], a[mt][3], b[1][0], b[1][1]);
                mma16816(acc[mt][3], a[mt][0], a[mt][1], a[mt][2], a[mt][3], b[1][2], b[1][3]);
            }
        }

        // ---- epilogue: bias + ReLU + pool in registers, shfl-reduce
        float ps[8];
#pragma unroll
        for (int i = 0; i < 8; i++) ps[i] = 0.0f;
#pragma unroll
        for (int mt = 0; mt < 2; mt++)
#pragma unroll
            for (int nt = 0; nt < 4; nt++)
#pragma unroll
                for (int h = 0; h < 2; h++) {
                    ps[nt * 2 + 0] += fmaxf(acc[mt][nt][2 * h + 0] + bvals[nt * 2 + 0], 0.0f);
                    ps[nt * 2 + 1] += fmaxf(acc[mt][nt][2 * h + 1] + bvals[nt * 2 + 1], 0.0f);
                }
#pragma unroll
        for (int off = 4; off < 32; off <<= 1)
#pragma unroll
            for (int i = 0; i < 8; i++)
                ps[i] += __shfl_xor_sync(0xFFFFFFFFu, ps[i], off);

        if (lane < 4) {
#pragma unroll
            for (int nt = 0; nt < 4; nt++) {
                spool[wm * 64 + wn * 32 + nt * 8 + lane * 2 + 0] = ps[nt * 2 + 0];
                spool[wm * 64 + wn * 32 + nt * 8 + lane * 2 + 1] = ps[nt * 2 + 1];
            }
        }
        __syncthreads();

        if (tid < OCN)
            g_partial[(size_t)t * OCN + tid] =
                spool[tid] + spool[64 + tid] + spool[128 + tid] + spool[192 + tid];

        if (havenext) store_regs(it ^ 1);     // fill the other buffer
        __syncthreads();                       // staging ready + spool consumed
    }
}

// ---------------------------------------------------------------- graph MLP
__global__ __launch_bounds__(256, 1)
void mlp_kernel(const float* __restrict__ ew1, const float* __restrict__ eb1,
                const float* __restrict__ ew2, const float* __restrict__ eb2,
                const float* __restrict__ ow1, const float* __restrict__ ob1,
                const float* __restrict__ ow2, const float* __restrict__ ob2,
                float* __restrict__ out) {
    extern __shared__ float s[];
    float* sw1  = s;              // 128*64
    float* sw2  = sw1 + 8192;     // 64*64
    float* so1  = sw2 + 4096;     // 64*64
    float* so2  = so1 + 4096;     // 64
    float* sb1  = so2 + 64;       // 64
    float* sb2  = sb1 + 64;       // 64
    float* sb3  = sb2 + 64;       // 64
    float* node = sb3 + 64;       // 4*64
    float* us   = node + 256;     // 4*64
    float* vs   = us + 256;       // 4*64
    float* h1s  = vs + 256;       // 16*64
    float* h2s  = h1s + 1024;     // 16*64
    float* msg  = h2s + 1024;     // 4*64
    float* o1s  = msg + 256;      // 4*64

    const int b = blockIdx.x;
    const int tid = threadIdx.x;
    const int p = tid >> 6;
    const int h = tid & 63;

    for (int i = tid; i < 8192; i += 256) sw1[i] = ew1[i];
    for (int i = tid; i < 4096; i += 256) sw2[i] = ew2[i];
    for (int i = tid; i < 4096; i += 256) so1[i] = ow1[i];
    if (tid < 64) {
        so2[tid] = ow2[tid];
        sb1[tid] = eb1[tid];
        sb2[tid] = eb2[tid];
        sb3[tid] = ob1[tid];
    }

    // nodes[p][h] = mean over 32 tile partials / 4096
    {
        const float* gp = &g_partial[(size_t)((p * BB + b) * 32) * OCN + h];
        float sum = 0.0f;
#pragma unroll
        for (int k = 0; k < 32; k++) sum += gp[k * OCN];
        node[p * 64 + h] = sum * (1.0f / 4096.0f);
    }
    __syncthreads();

    // u/v factorization of edge layer 1: h1[(i,j)] = relu(u_i + v_j + b1)
    {
        float uu = 0.0f, vv = 0.0f;
        for (int k = 0; k < 64; k++) {
            float nk = node[p * 64 + k];
            uu = fmaf(nk, sw1[k * 64 + h], uu);
            vv = fmaf(nk, sw1[(64 + k) * 64 + h], vv);
        }
        us[p * 64 + h] = uu;
        vs[p * 64 + h] = vv;
    }
    __syncthreads();

#pragma unroll
    for (int e4 = 0; e4 < 4; e4++)
        h1s[(e4 * 4 + p) * 64 + h] =
            fmaxf(us[e4 * 64 + h] + vs[p * 64 + h] + sb1[h], 0.0f);
    __syncthreads();

    // h2[e] = relu(b2 + h1[e] . W2)
    {
        float acc[4];
#pragma unroll
        for (int e4 = 0; e4 < 4; e4++) acc[e4] = sb2[h];
        for (int k = 0; k < 64; k++) {
            float w = sw2[k * 64 + h];
#pragma unroll
            for (int e4 = 0; e4 < 4; e4++)
                acc[e4] = fmaf(h1s[(e4 * 4 + p) * 64 + k], w, acc[e4]);
        }
#pragma unroll
        for (int e4 = 0; e4 < 4; e4++)
            h2s[(e4 * 4 + p) * 64 + h] = fmaxf(acc[e4], 0.0f);
    }
    __syncthreads();

    {
        float m = 0.25f * (h2s[(0 * 4 + p) * 64 + h] + h2s[(1 * 4 + p) * 64 + h] +
                           h2s[(2 * 4 + p) * 64 + h] + h2s[(3 * 4 + p) * 64 + h]);
        msg[p * 64 + h] = m;
    }
    __syncthreads();
    {
        float s3 = sb3[h];
        for (int k = 0; k < 64; k++)
            s3 = fmaf(msg[p * 64 + k], so1[k * 64 + h], s3);
        o1s[p * 64 + h] = fmaxf(s3, 0.0f);
    }
    __syncthreads();

    if (tid < PP) {
        float s4 = __ldg(&ob2[0]);
        for (int k = 0; k < 64; k++)
            s4 = fmaf(o1s[tid * 64 + k], so2[k], s4);
        out[b * PP + tid] = s4;
    }
}

// ---------------------------------------------------------------- launch
extern "C" void kernel_launch(void* const* d_in, const int* in_sizes, int n_in,
                              void* d_out, int out_size) {
    const float* x      = (const float*)d_in[0];
    const float* conv_w = (const float*)d_in[1];
    const float* conv_b = (const float*)d_in[2];
    const float* e_w1   = (const float*)d_in[3];
    const float* e_b1   = (const float*)d_in[4];
    const float* e_w2   = (const float*)d_in[5];
    const float* e_b2   = (const float*)d_in[6];
    const float* o_w1   = (const float*)d_in[7];
    const float* o_b1   = (const float*)d_in[8];
    const float* o_w2   = (const float*)d_in[9];
    const float* o_b2   = (const float*)d_in[10];
    float* out = (float*)d_out;

    cudaFuncSetAttribute(conv_mma_kernel,
                         cudaFuncAttributeMaxDynamicSharedMemorySize, SMEM_BYTES);
    const int smemB = (8192 + 4096 + 4096 + 64 * 4 + 256 * 3 + 1024 * 2 + 256 * 2) *
                      (int)sizeof(float);
    cudaFuncSetAttribute(mlp_kernel,
                         cudaFuncAttributeMaxDynamicSharedMemorySize, smemB);

    conv_mma_kernel<<<GRIDC, 256, SMEM_BYTES>>>(x, conv_w, conv_b);
    mlp_kernel<<<BB, 256, smemB>>>(e_w1, e_b1, e_w2, e_b2,
                                   o_w1, o_b1, o_w2, o_b2, out);
}

// round 8
// speedup vs baseline: 7.8751x; 1.0626x over previous
#include <cuda_runtime.h>
#include <cuda_bf16.h>
#include <cstdint>

// ---------------------------------------------------------------- constants
#define HH     64
#define WW     64
#define CIN    32
#define OCN    64
#define NIMG   512
#define NT2    8192           // 512 images * 16 row-quads (256 pixels each)
#define GRIDC  296            // 2 CTAs per SM
#define PP     4
#define BB     128

#define LDK    296            // B tile padded K stride (elements)
#define LDKB   592            // bytes
#define ST_COL 80             // bytes per (row,col) slot (32 bf16 + 16B pad)
#define ST_ROW (66 * ST_COL)  // 5280 bytes per staging row
#define ST_BYTES (6 * ST_ROW) // 31680: 6 staged rows (4 out rows + 2 halo)

// SMEM layout (bytes)
#define SM_BIAS   0           // 64 f32  (256 B)
#define SM_POOL   256         // 256 f32 (1024 B)
#define ST_OFF    1280        // staging -> ends 32960
#define B_OFF     32960       // 64*592 = 37888 -> ends 70848
#define SMEM_BYTES 70848

__device__ float g_partial[NT2 * OCN];   // per-tile pooled sums

// ---------------------------------------------------------------- helpers
__device__ __forceinline__ uint32_t smem_u32(const void* p) {
    uint32_t a;
    asm("{ .reg .u64 t; cvta.to.shared.u64 t, %1; cvt.u32.u64 %0, t; }"
        : "=r"(a) : "l"(p));
    return a;
}

__device__ __forceinline__ void ldsm_x4(uint32_t& r0, uint32_t& r1,
                                        uint32_t& r2, uint32_t& r3,
                                        uint32_t addr) {
    asm volatile("ldmatrix.sync.aligned.m8n8.x4.shared.b16 {%0,%1,%2,%3}, [%4];"
                 : "=r"(r0), "=r"(r1), "=r"(r2), "=r"(r3) : "r"(addr));
}

__device__ __forceinline__ void mma16816(float* c,
                                         uint32_t a0, uint32_t a1, uint32_t a2, uint32_t a3,
                                         uint32_t b0, uint32_t b1) {
    asm volatile(
        "mma.sync.aligned.m16n8k16.row.col.f32.bf16.bf16.f32 "
        "{%0,%1,%2,%3}, {%4,%5,%6,%7}, {%8,%9}, {%0,%1,%2,%3};"
        : "+f"(c[0]), "+f"(c[1]), "+f"(c[2]), "+f"(c[3])
        : "r"(a0), "r"(a1), "r"(a2), "r"(a3), "r"(b0), "r"(b1));
}

__device__ __forceinline__ uint32_t pack_bf16x2(float a, float b) {
    __nv_bfloat162 h = __floats2bfloat162_rn(a, b);
    return *(uint32_t*)&h;
}

// ---------------------------------------------------------------- conv (HMMA)
__global__ __launch_bounds__(256, 2)
void conv_mma_kernel(const float* __restrict__ x, const float* __restrict__ cw,
                     const float* __restrict__ cb) {
    extern __shared__ char smem[];
    const uint32_t sbase = smem_u32(smem);
    const int tid  = threadIdx.x;
    const int wid  = tid >> 5;
    const int lane = tid & 31;

    float* sbias = (float*)(smem + SM_BIAS);
    float* spool = (float*)(smem + SM_POOL);
    char*  st    = smem + ST_OFF;

    if (tid < OCN) sbias[tid] = cb[tid];

    // Build B from conv_w: B[oc][tap*32+ic] = bf16(cw[oc][ic][tap])
    {
        __nv_bfloat16* bw = (__nv_bfloat16*)(smem + B_OFF);
        for (int i = tid; i < OCN * 288; i += 256) {
            int oc = i / 288, k = i - oc * 288;
            int tap = k >> 5, ic = k & 31;
            bw[oc * LDK + k] = __float2bfloat16(cw[oc * 288 + ic * 9 + tap]);
        }
    }
    __syncthreads();

    // Warp geometry: warp = 64 pixels (output row wm) x 32 oc (wn half)
    const int wm = wid & 3;
    const int wn = wid >> 2;
    const uint32_t bBase = sbase + B_OFF +
        (wn * 32 + ((lane & 7) | ((lane & 16) >> 1))) * LDKB + ((lane >> 3) & 1) * 16;

    uint32_t stA[4];
#pragma unroll
    for (int mt = 0; mt < 4; mt++)
        stA[mt] = sbase + ST_OFF + wm * ST_ROW + (mt * 16 + (lane & 15)) * ST_COL;

    float bvals[8];
#pragma unroll
    for (int nt = 0; nt < 4; nt++)
#pragma unroll
        for (int c = 0; c < 2; c++)
            bvals[nt * 2 + c] = sbias[wn * 32 + nt * 8 + (lane & 3) * 2 + c];

    const int icp  = tid >> 4;          // 0..15 (ic pair)
    const int colg = tid & 15;          // 0..15 -> cols [4*colg, 4*colg+4)
    const bool isLo = (colg == 0);
    const bool isHi = (colg == 15);

    // Prefetch state: one stage (2 staged rows) raw fp32, 3 stages packed
    float    raw0[8], raw1[8];          // [rr*4+j] per channel
    uint32_t pk[3][8];

    auto load_stage = [&](int t, int s) {
        const int n  = t >> 4;
        const int r0 = (t & 15) * 4;
        const float* cc0 = x + (size_t)n * (CIN * HH * WW) + (2 * icp) * (HH * WW);
        const float* cc1 = cc0 + HH * WW;
#pragma unroll
        for (int rr = 0; rr < 2; rr++) {
            int gr = (r0 + 2 * s + rr - 1) & (HH - 1);
            float4 a = *(const float4*)(cc0 + gr * WW + 4 * colg);
            float4 b = *(const float4*)(cc1 + gr * WW + 4 * colg);
            raw0[rr * 4 + 0] = a.x; raw0[rr * 4 + 1] = a.y;
            raw0[rr * 4 + 2] = a.z; raw0[rr * 4 + 3] = a.w;
            raw1[rr * 4 + 0] = b.x; raw1[rr * 4 + 1] = b.y;
            raw1[rr * 4 + 2] = b.z; raw1[rr * 4 + 3] = b.w;
        }
    };
    auto pack_stage = [&](int s) {
#pragma unroll
        for (int i = 0; i < 8; i++) pk[s][i] = pack_bf16x2(raw0[i], raw1[i]);
    };
    auto store_stage = [&](int s) {
#pragma unroll
        for (int rr = 0; rr < 2; rr++) {
            int r = 2 * s + rr;
#pragma unroll
            for (int j = 0; j < 4; j++) {
                int c = 4 * colg + j;
                *(uint32_t*)(st + (r * 66 + c + 1) * ST_COL + 4 * icp) = pk[s][rr * 4 + j];
            }
            if (isLo)   // this thread owns src col 0 -> wrap staging col 65
                *(uint32_t*)(st + (r * 66 + 65) * ST_COL + 4 * icp) = pk[s][rr * 4 + 0];
            if (isHi)   // this thread owns src col 63 -> wrap staging col 0
                *(uint32_t*)(st + (r * 66 + 0) * ST_COL + 4 * icp) = pk[s][rr * 4 + 3];
        }
    };

    // ---- prime: fill staging for tile t0
    const int t0 = blockIdx.x;
#pragma unroll
    for (int s = 0; s < 3; s++) { load_stage(t0, s); pack_stage(s); store_stage(s); }
    __syncthreads();

    const int h16 = (lane >> 4);

    for (int t = t0; t < NT2; t += GRIDC) {
        const int tn = t + GRIDC;
        const bool hn = (tn < NT2);

        float acc[4][4][4];
#pragma unroll
        for (int mt = 0; mt < 4; mt++)
#pragma unroll
            for (int nt = 0; nt < 4; nt++)
#pragma unroll
                for (int e = 0; e < 4; e++) acc[mt][nt][e] = 0.0f;

        auto do_kstep = [&](int kk) {
            const int u   = 2 * kk + h16;
            const int tap = u >> 2;
            const int sub = u & 3;
            const int dy  = tap / 3, dx = tap - dy * 3;
            const uint32_t aoff = (uint32_t)(dy * ST_ROW + dx * ST_COL + sub * 16);

            uint32_t a[4][4], b[2][4];
#pragma unroll
            for (int mt = 0; mt < 4; mt++)
                ldsm_x4(a[mt][0], a[mt][1], a[mt][2], a[mt][3], stA[mt] + aoff);
#pragma unroll
            for (int g = 0; g < 2; g++)
                ldsm_x4(b[g][0], b[g][1], b[g][2], b[g][3],
                        bBase + g * 16 * LDKB + kk * 32);
#pragma unroll
            for (int mt = 0; mt < 4; mt++) {
                mma16816(acc[mt][0], a[mt][0], a[mt][1], a[mt][2], a[mt][3], b[0][0], b[0][1]);
                mma16816(acc[mt][1], a[mt][0], a[mt][1], a[mt][2], a[mt][3], b[0][2], b[0][3]);
                mma16816(acc[mt][2], a[mt][0], a[mt][1], a[mt][2], a[mt][3], b[1][0], b[1][1]);
                mma16816(acc[mt][3], a[mt][0], a[mt][1], a[mt][2], a[mt][3], b[1][2], b[1][3]);
            }
        };

        // thirds: interleave next-tile loads with the k-loop
        if (hn) load_stage(tn, 0);
#pragma unroll
        for (int kk = 0; kk < 6; kk++) do_kstep(kk);
        if (hn) { pack_stage(0); load_stage(tn, 1); }
#pragma unroll
        for (int kk = 6; kk < 12; kk++) do_kstep(kk);
        if (hn) { pack_stage(1); load_stage(tn, 2); }
#pragma unroll
        for (int kk = 12; kk < 18; kk++) do_kstep(kk);
        if (hn) pack_stage(2);

        // ---- epilogue: bias + ReLU + pool in registers, shfl-reduce
        float ps[8];
#pragma unroll
        for (int i = 0; i < 8; i++) ps[i] = 0.0f;
#pragma unroll
        for (int mt = 0; mt < 4; mt++)
#pragma unroll
            for (int nt = 0; nt < 4; nt++)
#pragma unroll
                for (int h = 0; h < 2; h++) {
                    ps[nt * 2 + 0] += fmaxf(acc[mt][nt][2 * h + 0] + bvals[nt * 2 + 0], 0.0f);
                    ps[nt * 2 + 1] += fmaxf(acc[mt][nt][2 * h + 1] + bvals[nt * 2 + 1], 0.0f);
                }
#pragma unroll
        for (int off = 4; off < 32; off <<= 1)
#pragma unroll
            for (int i = 0; i < 8; i++)
                ps[i] += __shfl_xor_sync(0xFFFFFFFFu, ps[i], off);

        if (lane < 4) {
#pragma unroll
            for (int nt = 0; nt < 4; nt++) {
                spool[wm * 64 + wn * 32 + nt * 8 + lane * 2 + 0] = ps[nt * 2 + 0];
                spool[wm * 64 + wn * 32 + nt * 8 + lane * 2 + 1] = ps[nt * 2 + 1];
            }
        }
        __syncthreads();

        if (tid < OCN)
            g_partial[(size_t)t * OCN + tid] =
                spool[tid] + spool[64 + tid] + spool[128 + tid] + spool[192 + tid];

        if (hn) { store_stage(0); store_stage(1); store_stage(2); }
        __syncthreads();   // staging ready for next iter + spool consumed
    }
}

// ---------------------------------------------------------------- graph MLP
__global__ __launch_bounds__(256, 1)
void mlp_kernel(const float* __restrict__ ew1, const float* __restrict__ eb1,
                const float* __restrict__ ew2, const float* __restrict__ eb2,
                const float* __restrict__ ow1, const float* __restrict__ ob1,
                const float* __restrict__ ow2, const float* __restrict__ ob2,
                float* __restrict__ out) {
    extern __shared__ float s[];
    float* sw1  = s;              // 128*64
    float* sw2  = sw1 + 8192;     // 64*64
    float* so1  = sw2 + 4096;     // 64*64
    float* so2  = so1 + 4096;     // 64
    float* sb1  = so2 + 64;       // 64
    float* sb2  = sb1 + 64;       // 64
    float* sb3  = sb2 + 64;       // 64
    float* node = sb3 + 64;       // 4*64
    float* us   = node + 256;     // 4*64
    float* vs   = us + 256;       // 4*64
    float* h1s  = vs + 256;       // 16*64
    float* h2s  = h1s + 1024;     // 16*64
    float* msg  = h2s + 1024;     // 4*64
    float* o1s  = msg + 256;      // 4*64

    const int b = blockIdx.x;
    const int tid = threadIdx.x;
    const int p = tid >> 6;
    const int h = tid & 63;

    for (int i = tid; i < 8192; i += 256) sw1[i] = ew1[i];
    for (int i = tid; i < 4096; i += 256) sw2[i] = ew2[i];
    for (int i = tid; i < 4096; i += 256) so1[i] = ow1[i];
    if (tid < 64) {
        so2[tid] = ow2[tid];
        sb1[tid] = eb1[tid];
        sb2[tid] = eb2[tid];
        sb3[tid] = ob1[tid];
    }

    // nodes[p][h] = mean over 16 tile partials / 4096
    {
        const float* gp = &g_partial[(size_t)((p * BB + b) * 16) * OCN + h];
        float sum = 0.0f;
#pragma unroll
        for (int k = 0; k < 16; k++) sum += gp[k * OCN];
        node[p * 64 + h] = sum * (1.0f / 4096.0f);
    }
    __syncthreads();

    // u/v factorization of edge layer 1: h1[(i,j)] = relu(u_i + v_j + b1)
    {
        float uu = 0.0f, vv = 0.0f;
        for (int k = 0; k < 64; k++) {
            float nk = node[p * 64 + k];
            uu = fmaf(nk, sw1[k * 64 + h], uu);
            vv = fmaf(nk, sw1[(64 + k) * 64 + h], vv);
        }
        us[p * 64 + h] = uu;
        vs[p * 64 + h] = vv;
    }
    __syncthreads();

#pragma unroll
    for (int e4 = 0; e4 < 4; e4++)
        h1s[(e4 * 4 + p) * 64 + h] =
            fmaxf(us[e4 * 64 + h] + vs[p * 64 + h] + sb1[h], 0.0f);
    __syncthreads();

    // h2[e] = relu(b2 + h1[e] . W2)
    {
        float acc[4];
#pragma unroll
        for (int e4 = 0; e4 < 4; e4++) acc[e4] = sb2[h];
        for (int k = 0; k < 64; k++) {
            float w = sw2[k * 64 + h];
#pragma unroll
            for (int e4 = 0; e4 < 4; e4++)
                acc[e4] = fmaf(h1s[(e4 * 4 + p) * 64 + k], w, acc[e4]);
        }
#pragma unroll
        for (int e4 = 0; e4 < 4; e4++)
            h2s[(e4 * 4 + p) * 64 + h] = fmaxf(acc[e4], 0.0f);
    }
    __syncthreads();

    {
        float m = 0.25f * (h2s[(0 * 4 + p) * 64 + h] + h2s[(1 * 4 + p) * 64 + h] +
                           h2s[(2 * 4 + p) * 64 + h] + h2s[(3 * 4 + p) * 64 + h]);
        msg[p * 64 + h] = m;
    }
    __syncthreads();
    {
        float s3 = sb3[h];
        for (int k = 0; k < 64; k++)
            s3 = fmaf(msg[p * 64 + k], so1[k * 64 + h], s3);
        o1s[p * 64 + h] = fmaxf(s3, 0.0f);
    }
    __syncthreads();

    if (tid < PP) {
        float s4 = __ldg(&ob2[0]);
        for (int k = 0; k < 64; k++)
            s4 = fmaf(o1s[tid * 64 + k], so2[k], s4);
        out[b * PP + tid] = s4;
    }
}

// ---------------------------------------------------------------- launch
extern "C" void kernel_launch(void* const* d_in, const int* in_sizes, int n_in,
                              void* d_out, int out_size) {
    const float* x      = (const float*)d_in[0];
    const float* conv_w = (const float*)d_in[1];
    const float* conv_b = (const float*)d_in[2];
    const float* e_w1   = (const float*)d_in[3];
    const float* e_b1   = (const float*)d_in[4];
    const float* e_w2   = (const float*)d_in[5];
    const float* e_b2   = (const float*)d_in[6];
    const float* o_w1   = (const float*)d_in[7];
    const float* o_b1   = (const float*)d_in[8];
    const float* o_w2   = (const float*)d_in[9];
    const float* o_b2   = (const float*)d_in[10];
    float* out = (float*)d_out;

    cudaFuncSetAttribute(conv_mma_kernel,
                         cudaFuncAttributeMaxDynamicSharedMemorySize, SMEM_BYTES);
    const int smemB = (8192 + 4096 + 4096 + 64 * 4 + 256 * 3 + 1024 * 2 + 256 * 2) *
                      (int)sizeof(float);
    cudaFuncSetAttribute(mlp_kernel,
                         cudaFuncAttributeMaxDynamicSharedMemorySize, smemB);

    conv_mma_kernel<<<GRIDC, 256, SMEM_BYTES>>>(x, conv_w, conv_b);
    mlp_kernel<<<BB, 256, smemB>>>(e_w1, e_b1, e_w2, e_b2,
                                   o_w1, o_b1, o_w2, o_b2, out);
}

// round 9
// speedup vs baseline: 9.3603x; 1.1886x over previous
#include <cuda_runtime.h>
#include <cuda_bf16.h>
#include <cstdint>

// ---------------------------------------------------------------- constants
#define HH     64
#define WW     64
#define CIN    32
#define OCN    64
#define NIMG   512
#define NT3    4096           // 512 images * 8 row-octs (512 pixels each)
#define GRIDC  148            // 1 CTA per SM, occ=1 (128 acc regs/thread)
#define PP     4
#define BB     128

#define LDK    296            // B tile padded K stride (elements)
#define LDKB   592            // bytes
#define ST_COL 80             // bytes per (row,col) slot (32 bf16 + 16B pad)
#define ST_ROW (66 * ST_COL)  // 5280 bytes per staging row
#define ST_BYTES (10 * ST_ROW)// 52800: 10 staged rows (8 out rows + 2 halo)

// SMEM layout (bytes)
#define SM_BIAS   0           // 64 f32  (256 B)
#define SM_POOL   256         // 512 f32 (2048 B) -> ends 2304, pad to 2560
#define ST_OFF    2560        // 2 staging buffers: 2*52800 -> ends 108160
#define B_OFF     108160      // 64*592 = 37888 -> ends 146048
#define SMEM_BYTES 146048

__device__ float g_partial[NT3 * OCN];   // per-tile pooled sums

// ---------------------------------------------------------------- helpers
__device__ __forceinline__ uint32_t smem_u32(const void* p) {
    uint32_t a;
    asm("{ .reg .u64 t; cvta.to.shared.u64 t, %1; cvt.u32.u64 %0, t; }"
        : "=r"(a) : "l"(p));
    return a;
}

__device__ __forceinline__ void ldsm_x4(uint32_t& r0, uint32_t& r1,
                                        uint32_t& r2, uint32_t& r3,
                                        uint32_t addr) {
    asm volatile("ldmatrix.sync.aligned.m8n8.x4.shared.b16 {%0,%1,%2,%3}, [%4];"
                 : "=r"(r0), "=r"(r1), "=r"(r2), "=r"(r3) : "r"(addr));
}

__device__ __forceinline__ void mma16816(float* c,
                                         uint32_t a0, uint32_t a1, uint32_t a2, uint32_t a3,
                                         uint32_t b0, uint32_t b1) {
    asm volatile(
        "mma.sync.aligned.m16n8k16.row.col.f32.bf16.bf16.f32 "
        "{%0,%1,%2,%3}, {%4,%5,%6,%7}, {%8,%9}, {%0,%1,%2,%3};"
        : "+f"(c[0]), "+f"(c[1]), "+f"(c[2]), "+f"(c[3])
        : "r"(a0), "r"(a1), "r"(a2), "r"(a3), "r"(b0), "r"(b1));
}

__device__ __forceinline__ uint32_t pack_bf16x2(float a, float b) {
    __nv_bfloat162 h = __floats2bfloat162_rn(a, b);
    return *(uint32_t*)&h;
}

// ---------------------------------------------------------------- conv (HMMA)
__global__ __launch_bounds__(256, 1)
void conv_mma_kernel(const float* __restrict__ x, const float* __restrict__ cw,
                     const float* __restrict__ cb) {
    extern __shared__ char smem[];
    const uint32_t sbase = smem_u32(smem);
    const int tid  = threadIdx.x;
    const int wid  = tid >> 5;
    const int lane = tid & 31;

    float* sbias = (float*)(smem + SM_BIAS);
    float* spool = (float*)(smem + SM_POOL);
    char*  st    = smem + ST_OFF;

    if (tid < OCN) sbias[tid] = cb[tid];

    // Build B from conv_w: B[oc][tap*32+ic] = bf16(cw[oc][ic][tap])
    {
        __nv_bfloat16* bw = (__nv_bfloat16*)(smem + B_OFF);
        for (int i = tid; i < OCN * 288; i += 256) {
            int oc = i / 288, k = i - oc * 288;
            int tap = k >> 5, ic = k & 31;
            bw[oc * LDK + k] = __float2bfloat16(cw[oc * 288 + ic * 9 + tap]);
        }
    }

    // Warp geometry: warp wm owns output row wm (64 px) x ALL 64 oc
    const int wm = wid;                 // 0..7
    const uint32_t bBase = sbase + B_OFF +
        ((lane & 7) | ((lane & 16) >> 1)) * LDKB + ((lane >> 3) & 1) * 16;

    uint32_t stA[4];
#pragma unroll
    for (int mt = 0; mt < 4; mt++)
        stA[mt] = sbase + ST_OFF + wm * ST_ROW + (mt * 16 + (lane & 15)) * ST_COL;

    float bvals[16];
#pragma unroll
    for (int nt = 0; nt < 8; nt++)
#pragma unroll
        for (int c = 0; c < 2; c++)
            bvals[nt * 2 + c] = sbias[nt * 8 + (lane & 3) * 2 + c];

    const int icp  = tid >> 4;          // 0..15 (ic pair)
    const int colg = tid & 15;          // 0..15 -> cols [4*colg, 4*colg+4)
    const bool isLo = (colg == 0);
    const bool isHi = (colg == 15);

    // One staging stage (2 rows) in registers at a time
    float    raw0[8], raw1[8];
    uint32_t pk[8];

    auto load_stage = [&](int t, int s) {
        const int n  = t >> 3;
        const int r0 = (t & 7) * 8;
        const float* cc0 = x + (size_t)n * (CIN * HH * WW) + (2 * icp) * (HH * WW);
        const float* cc1 = cc0 + HH * WW;
#pragma unroll
        for (int rr = 0; rr < 2; rr++) {
            int gr = (r0 + 2 * s + rr - 1) & (HH - 1);
            float4 a = *(const float4*)(cc0 + gr * WW + 4 * colg);
            float4 b = *(const float4*)(cc1 + gr * WW + 4 * colg);
            raw0[rr * 4 + 0] = a.x; raw0[rr * 4 + 1] = a.y;
            raw0[rr * 4 + 2] = a.z; raw0[rr * 4 + 3] = a.w;
            raw1[rr * 4 + 0] = b.x; raw1[rr * 4 + 1] = b.y;
            raw1[rr * 4 + 2] = b.z; raw1[rr * 4 + 3] = b.w;
        }
    };
    auto pack_store = [&](int s, int buf) {
        char* stb = st + buf * ST_BYTES;
#pragma unroll
        for (int i = 0; i < 8; i++) pk[i] = pack_bf16x2(raw0[i], raw1[i]);
#pragma unroll
        for (int rr = 0; rr < 2; rr++) {
            int r = 2 * s + rr;
#pragma unroll
            for (int j = 0; j < 4; j++) {
                int c = 4 * colg + j;
                *(uint32_t*)(stb + (r * 66 + c + 1) * ST_COL + 4 * icp) = pk[rr * 4 + j];
            }
            if (isLo)   // owns src col 0 -> wrap staging col 65
                *(uint32_t*)(stb + (r * 66 + 65) * ST_COL + 4 * icp) = pk[rr * 4 + 0];
            if (isHi)   // owns src col 63 -> wrap staging col 0
                *(uint32_t*)(stb + (r * 66 + 0) * ST_COL + 4 * icp) = pk[rr * 4 + 3];
        }
    };

    // ---- prime buffer 0 with tile t0
    const int t0 = blockIdx.x;
#pragma unroll
    for (int s = 0; s < 5; s++) { load_stage(t0, s); pack_store(s, 0); }
    __syncthreads();

    const int h16 = (lane >> 4);
    int it = 0;
    for (int t = t0; t < NT3; t += GRIDC, it ^= 1) {
        const int tn = t + GRIDC;
        const bool hn = (tn < NT3);
        const uint32_t bufoff = (uint32_t)(it * ST_BYTES);
        const int nb = it ^ 1;

        float acc[4][8][4];
#pragma unroll
        for (int mt = 0; mt < 4; mt++)
#pragma unroll
            for (int nt = 0; nt < 8; nt++)
#pragma unroll
                for (int e = 0; e < 4; e++) acc[mt][nt][e] = 0.0f;

        auto do_kstep = [&](int kk) {
            const int u   = 2 * kk + h16;
            const int tap = u >> 2;
            const int sub = u & 3;
            const int dy  = tap / 3, dx = tap - dy * 3;
            const uint32_t aoff = bufoff +
                (uint32_t)(dy * ST_ROW + dx * ST_COL + sub * 16);

            uint32_t a[4][4], b[4][4];
#pragma unroll
            for (int mt = 0; mt < 4; mt++)
                ldsm_x4(a[mt][0], a[mt][1], a[mt][2], a[mt][3], stA[mt] + aoff);
#pragma unroll
            for (int g = 0; g < 4; g++)
                ldsm_x4(b[g][0], b[g][1], b[g][2], b[g][3],
                        bBase + g * 16 * LDKB + kk * 32);
#pragma unroll
            for (int mt = 0; mt < 4; mt++)
#pragma unroll
                for (int g = 0; g < 4; g++) {
                    mma16816(acc[mt][2 * g + 0], a[mt][0], a[mt][1], a[mt][2], a[mt][3],
                             b[g][0], b[g][1]);
                    mma16816(acc[mt][2 * g + 1], a[mt][0], a[mt][1], a[mt][2], a[mt][3],
                             b[g][2], b[g][3]);
                }
        };

        // Interleave next-tile staging (5 stages) with the 18 k-steps
        if (hn) load_stage(tn, 0);
#pragma unroll
        for (int kk = 0; kk < 3; kk++) do_kstep(kk);
        if (hn) { pack_store(0, nb); load_stage(tn, 1); }
#pragma unroll
        for (int kk = 3; kk < 7; kk++) do_kstep(kk);
        if (hn) { pack_store(1, nb); load_stage(tn, 2); }
#pragma unroll
        for (int kk = 7; kk < 11; kk++) do_kstep(kk);
        if (hn) { pack_store(2, nb); load_stage(tn, 3); }
#pragma unroll
        for (int kk = 11; kk < 15; kk++) do_kstep(kk);
        if (hn) { pack_store(3, nb); load_stage(tn, 4); }
#pragma unroll
        for (int kk = 15; kk < 18; kk++) do_kstep(kk);
        if (hn) pack_store(4, nb);

        // ---- epilogue: bias + ReLU + pool, shfl-reduce over pixel rows
        float ps[16];
#pragma unroll
        for (int i = 0; i < 16; i++) ps[i] = 0.0f;
#pragma unroll
        for (int mt = 0; mt < 4; mt++)
#pragma unroll
            for (int nt = 0; nt < 8; nt++)
#pragma unroll
                for (int h = 0; h < 2; h++) {
                    ps[nt * 2 + 0] += fmaxf(acc[mt][nt][2 * h + 0] + bvals[nt * 2 + 0], 0.0f);
                    ps[nt * 2 + 1] += fmaxf(acc[mt][nt][2 * h + 1] + bvals[nt * 2 + 1], 0.0f);
                }
#pragma unroll
        for (int off = 4; off < 32; off <<= 1)
#pragma unroll
            for (int i = 0; i < 16; i++)
                ps[i] += __shfl_xor_sync(0xFFFFFFFFu, ps[i], off);

        if (lane < 4) {
#pragma unroll
            for (int nt = 0; nt < 8; nt++) {
                spool[wm * 64 + nt * 8 + lane * 2 + 0] = ps[nt * 2 + 0];
                spool[wm * 64 + nt * 8 + lane * 2 + 1] = ps[nt * 2 + 1];
            }
        }
        __syncthreads();

        if (tid < OCN) {
            float s = 0.0f;
#pragma unroll
            for (int w = 0; w < 8; w++) s += spool[w * 64 + tid];
            g_partial[(size_t)t * OCN + tid] = s;
        }
        __syncthreads();   // spool consumed + next staging buffer published
    }
}

// ---------------------------------------------------------------- graph MLP
__global__ __launch_bounds__(256, 1)
void mlp_kernel(const float* __restrict__ ew1, const float* __restrict__ eb1,
                const float* __restrict__ ew2, const float* __restrict__ eb2,
                const float* __restrict__ ow1, const float* __restrict__ ob1,
                const float* __restrict__ ow2, const float* __restrict__ ob2,
                float* __restrict__ out) {
    extern __shared__ float s[];
    float* sw1  = s;              // 128*64
    float* sw2  = sw1 + 8192;     // 64*64
    float* so1  = sw2 + 4096;     // 64*64
    float* so2  = so1 + 4096;     // 64
    float* sb1  = so2 + 64;       // 64
    float* sb2  = sb1 + 64;       // 64
    float* sb3  = sb2 + 64;       // 64
    float* node = sb3 + 64;       // 4*64
    float* us   = node + 256;     // 4*64
    float* vs   = us + 256;       // 4*64
    float* h1s  = vs + 256;       // 16*64
    float* h2s  = h1s + 1024;     // 16*64
    float* msg  = h2s + 1024;     // 4*64
    float* o1s  = msg + 256;      // 4*64

    const int b = blockIdx.x;
    const int tid = threadIdx.x;
    const int p = tid >> 6;
    const int h = tid & 63;

    for (int i = tid; i < 8192; i += 256) sw1[i] = ew1[i];
    for (int i = tid; i < 4096; i += 256) sw2[i] = ew2[i];
    for (int i = tid; i < 4096; i += 256) so1[i] = ow1[i];
    if (tid < 64) {
        so2[tid] = ow2[tid];
        sb1[tid] = eb1[tid];
        sb2[tid] = eb2[tid];
        sb3[tid] = ob1[tid];
    }

    // nodes[p][h] = mean over 8 tile partials / 4096
    {
        const float* gp = &g_partial[(size_t)((p * BB + b) * 8) * OCN + h];
        float sum = 0.0f;
#pragma unroll
        for (int k = 0; k < 8; k++) sum += gp[k * OCN];
        node[p * 64 + h] = sum * (1.0f / 4096.0f);
    }
    __syncthreads();

    // u/v factorization of edge layer 1: h1[(i,j)] = relu(u_i + v_j + b1)
    {
        float uu = 0.0f, vv = 0.0f;
        for (int k = 0; k < 64; k++) {
            float nk = node[p * 64 + k];
            uu = fmaf(nk, sw1[k * 64 + h], uu);
            vv = fmaf(nk, sw1[(64 + k) * 64 + h], vv);
        }
        us[p * 64 + h] = uu;
        vs[p * 64 + h] = vv;
    }
    __syncthreads();

#pragma unroll
    for (int e4 = 0; e4 < 4; e4++)
        h1s[(e4 * 4 + p) * 64 + h] =
            fmaxf(us[e4 * 64 + h] + vs[p * 64 + h] + sb1[h], 0.0f);
    __syncthreads();

    // h2[e] = relu(b2 + h1[e] . W2)
    {
        float acc[4];
#pragma unroll
        for (int e4 = 0; e4 < 4; e4++) acc[e4] = sb2[h];
        for (int k = 0; k < 64; k++) {
            float w = sw2[k * 64 + h];
#pragma unroll
            for (int e4 = 0; e4 < 4; e4++)
                acc[e4] = fmaf(h1s[(e4 * 4 + p) * 64 + k], w, acc[e4]);
        }
#pragma unroll
        for (int e4 = 0; e4 < 4; e4++)
            h2s[(e4 * 4 + p) * 64 + h] = fmaxf(acc[e4], 0.0f);
    }
    __syncthreads();

    {
        float m = 0.25f * (h2s[(0 * 4 + p) * 64 + h] + h2s[(1 * 4 + p) * 64 + h] +
                           h2s[(2 * 4 + p) * 64 + h] + h2s[(3 * 4 + p) * 64 + h]);
        msg[p * 64 + h] = m;
    }
    __syncthreads();
    {
        float s3 = sb3[h];
        for (int k = 0; k < 64; k++)
            s3 = fmaf(msg[p * 64 + k], so1[k * 64 + h], s3);
        o1s[p * 64 + h] = fmaxf(s3, 0.0f);
    }
    __syncthreads();

    if (tid < PP) {
        float s4 = __ldg(&ob2[0]);
        for (int k = 0; k < 64; k++)
            s4 = fmaf(o1s[tid * 64 + k], so2[k], s4);
        out[b * PP + tid] = s4;
    }
}

// ---------------------------------------------------------------- launch
extern "C" void kernel_launch(void* const* d_in, const int* in_sizes, int n_in,
                              void* d_out, int out_size) {
    const float* x      = (const float*)d_in[0];
    const float* conv_w = (const float*)d_in[1];
    const float* conv_b = (const float*)d_in[2];
    const float* e_w1   = (const float*)d_in[3];
    const float* e_b1   = (const float*)d_in[4];
    const float* e_w2   = (const float*)d_in[5];
    const float* e_b2   = (const float*)d_in[6];
    const float* o_w1   = (const float*)d_in[7];
    const float* o_b1   = (const float*)d_in[8];
    const float* o_w2   = (const float*)d_in[9];
    const float* o_b2   = (const float*)d_in[10];
    float* out = (float*)d_out;

    cudaFuncSetAttribute(conv_mma_kernel,
                         cudaFuncAttributeMaxDynamicSharedMemorySize, SMEM_BYTES);
    const int smemB = (8192 + 4096 + 4096 + 64 * 4 + 256 * 3 + 1024 * 2 + 256 * 2) *
                      (int)sizeof(float);
    cudaFuncSetAttribute(mlp_kernel,
                         cudaFuncAttributeMaxDynamicSharedMemorySize, smemB);

    conv_mma_kernel<<<GRIDC, 256, SMEM_BYTES>>>(x, conv_w, conv_b);
    mlp_kernel<<<BB, 256, smemB>>>(e_w1, e_b1, e_w2, e_b2,
                                   o_w1, o_b1, o_w2, o_b2, out);
}

// round 10
// speedup vs baseline: 9.6557x; 1.0316x over previous
#include <cuda_runtime.h>
#include <cuda_bf16.h>
#include <cstdint>

// ---------------------------------------------------------------- constants
#define HH     64
#define WW     64
#define CIN    32
#define OCN    64
#define NIMG   512
#define NT3    4096           // 512 images * 8 row-octs (512 pixels each)
#define GRIDC  148            // 1 CTA per SM
#define PP     4
#define BB     128

#define LDK    296            // B tile padded K stride (elements)
#define LDKB   592            // bytes
#define ST_COL 80             // bytes per (row,col) slot (32 bf16 + 16B pad)
#define ST_ROW (66 * ST_COL)  // 5280 bytes per staging row
#define ST_BYTES (10 * ST_ROW)// 52800: 10 staged rows (8 out rows + 2 halo)

// SMEM layout (bytes)
#define SM_BIAS   0           // 64 f32  (256 B)
#define SM_POOL   256         // 512 f32 (2048 B) -> ends 2304, pad to 2560
#define ST_OFF    2560        // 2 staging buffers: 2*52800 -> ends 108160
#define B_OFF     108160      // 64*592 = 37888 -> ends 146048
#define SMEM_BYTES 146048

__device__ float g_partial[NT3 * OCN];   // per-tile pooled sums

// ---------------------------------------------------------------- helpers
__device__ __forceinline__ uint32_t smem_u32(const void* p) {
    uint32_t a;
    asm("{ .reg .u64 t; cvta.to.shared.u64 t, %1; cvt.u32.u64 %0, t; }"
        : "=r"(a) : "l"(p));
    return a;
}

__device__ __forceinline__ void ldsm_x4(uint32_t& r0, uint32_t& r1,
                                        uint32_t& r2, uint32_t& r3,
                                        uint32_t addr) {
    asm volatile("ldmatrix.sync.aligned.m8n8.x4.shared.b16 {%0,%1,%2,%3}, [%4];"
                 : "=r"(r0), "=r"(r1), "=r"(r2), "=r"(r3) : "r"(addr));
}

__device__ __forceinline__ void mma16816(float* c,
                                         uint32_t a0, uint32_t a1, uint32_t a2, uint32_t a3,
                                         uint32_t b0, uint32_t b1) {
    asm volatile(
        "mma.sync.aligned.m16n8k16.row.col.f32.bf16.bf16.f32 "
        "{%0,%1,%2,%3}, {%4,%5,%6,%7}, {%8,%9}, {%0,%1,%2,%3};"
        : "+f"(c[0]), "+f"(c[1]), "+f"(c[2]), "+f"(c[3])
        : "r"(a0), "r"(a1), "r"(a2), "r"(a3), "r"(b0), "r"(b1));
}

__device__ __forceinline__ uint32_t pack_bf16x2(float a, float b) {
    __nv_bfloat162 h = __floats2bfloat162_rn(a, b);
    return *(uint32_t*)&h;
}

// ---------------------------------------------------------------- conv (HMMA)
__global__ __launch_bounds__(256, 1)
void conv_mma_kernel(const float* __restrict__ x, const float* __restrict__ cw,
                     const float* __restrict__ cb) {
    extern __shared__ char smem[];
    const uint32_t sbase = smem_u32(smem);
    const int tid  = threadIdx.x;
    const int wid  = tid >> 5;
    const int lane = tid & 31;

    float* sbias = (float*)(smem + SM_BIAS);
    float* spool = (float*)(smem + SM_POOL);
    char*  st    = smem + ST_OFF;

    if (tid < OCN) sbias[tid] = cb[tid];

    // Build B from conv_w: B[oc][tap*32+ic] = bf16(cw[oc][ic][tap])
    {
        __nv_bfloat16* bw = (__nv_bfloat16*)(smem + B_OFF);
        for (int i = tid; i < OCN * 288; i += 256) {
            int oc = i / 288, k = i - oc * 288;
            int tap = k >> 5, ic = k & 31;
            bw[oc * LDK + k] = __float2bfloat16(cw[oc * 288 + ic * 9 + tap]);
        }
    }

    // Warp geometry: warp wm owns output row wm (64 px) x ALL 64 oc
    const int wm = wid;                 // 0..7
    const uint32_t bBase = sbase + B_OFF +
        ((lane & 7) | ((lane & 16) >> 1)) * LDKB + ((lane >> 3) & 1) * 16;

    uint32_t stA[4];
#pragma unroll
    for (int mt = 0; mt < 4; mt++)
        stA[mt] = sbase + ST_OFF + wm * ST_ROW + (mt * 16 + (lane & 15)) * ST_COL;

    const int icp  = tid >> 4;          // 0..15 (ic pair)
    const int colg = tid & 15;          // 0..15 -> cols [4*colg, 4*colg+4)
    const bool isLo = (colg == 0);
    const bool isHi = (colg == 15);

    // One staging stage (2 rows) in registers at a time
    float    raw0[8], raw1[8];
    uint32_t pk[8];

    auto load_stage = [&](int t, int s) {
        const int n  = t >> 3;
        const int r0 = (t & 7) * 8;
        const float* cc0 = x + (size_t)n * (CIN * HH * WW) + (2 * icp) * (HH * WW);
        const float* cc1 = cc0 + HH * WW;
#pragma unroll
        for (int rr = 0; rr < 2; rr++) {
            int gr = (r0 + 2 * s + rr - 1) & (HH - 1);
            float4 a = *(const float4*)(cc0 + gr * WW + 4 * colg);
            float4 b = *(const float4*)(cc1 + gr * WW + 4 * colg);
            raw0[rr * 4 + 0] = a.x; raw0[rr * 4 + 1] = a.y;
            raw0[rr * 4 + 2] = a.z; raw0[rr * 4 + 3] = a.w;
            raw1[rr * 4 + 0] = b.x; raw1[rr * 4 + 1] = b.y;
            raw1[rr * 4 + 2] = b.z; raw1[rr * 4 + 3] = b.w;
        }
    };
    auto pack_store = [&](int s, int buf) {
        char* stb = st + buf * ST_BYTES;
#pragma unroll
        for (int i = 0; i < 8; i++) pk[i] = pack_bf16x2(raw0[i], raw1[i]);
#pragma unroll
        for (int rr = 0; rr < 2; rr++) {
            int r = 2 * s + rr;
#pragma unroll
            for (int j = 0; j < 4; j++) {
                int c = 4 * colg + j;
                *(uint32_t*)(stb + (r * 66 + c + 1) * ST_COL + 4 * icp) = pk[rr * 4 + j];
            }
            if (isLo)
                *(uint32_t*)(stb + (r * 66 + 65) * ST_COL + 4 * icp) = pk[rr * 4 + 0];
            if (isHi)
                *(uint32_t*)(stb + (r * 66 + 0) * ST_COL + 4 * icp) = pk[rr * 4 + 3];
        }
    };

    // ---- prime buffer 0 with tile t0
    const int t0 = blockIdx.x;
#pragma unroll
    for (int s = 0; s < 5; s++) { load_stage(t0, s); pack_store(s, 0); }
    __syncthreads();

    const int h16 = (lane >> 4);
    int it = 0;
    for (int t = t0; t < NT3; t += GRIDC, it ^= 1) {
        const int tn = t + GRIDC;
        const bool hn = (tn < NT3);
        const uint32_t bufoff = (uint32_t)(it * ST_BYTES);
        const int nb = it ^ 1;

        float acc[4][8][4];
#pragma unroll
        for (int mt = 0; mt < 4; mt++)
#pragma unroll
            for (int nt = 0; nt < 8; nt++)
#pragma unroll
                for (int e = 0; e < 4; e++) acc[mt][nt][e] = 0.0f;

        // pipelined fragments: pb = kk & 1
        uint32_t af[2][4][4], bf[2][4][4];

        auto ldsm_all = [&](int kk, int pb) {
            const int u   = 2 * kk + h16;
            const int tap = u >> 2;
            const int sub = u & 3;
            const int dy  = tap / 3, dx = tap - dy * 3;
            const uint32_t aoff = bufoff +
                (uint32_t)(dy * ST_ROW + dx * ST_COL + sub * 16);
#pragma unroll
            for (int mt = 0; mt < 4; mt++)
                ldsm_x4(af[pb][mt][0], af[pb][mt][1], af[pb][mt][2], af[pb][mt][3],
                        stA[mt] + aoff);
#pragma unroll
            for (int g = 0; g < 4; g++)
                ldsm_x4(bf[pb][g][0], bf[pb][g][1], bf[pb][g][2], bf[pb][g][3],
                        bBase + g * 16 * LDKB + kk * 32);
        };
        auto mma_all = [&](int pb) {
#pragma unroll
            for (int mt = 0; mt < 4; mt++)
#pragma unroll
                for (int g = 0; g < 4; g++) {
                    mma16816(acc[mt][2 * g + 0],
                             af[pb][mt][0], af[pb][mt][1], af[pb][mt][2], af[pb][mt][3],
                             bf[pb][g][0], bf[pb][g][1]);
                    mma16816(acc[mt][2 * g + 1],
                             af[pb][mt][0], af[pb][mt][1], af[pb][mt][2], af[pb][mt][3],
                             bf[pb][g][2], bf[pb][g][3]);
                }
        };

        // ---- pipelined k-loop with interleaved next-tile staging
        ldsm_all(0, 0);
        if (hn) load_stage(tn, 0);
#pragma unroll
        for (int kk = 0; kk < 3; kk++) { ldsm_all(kk + 1, (kk + 1) & 1); mma_all(kk & 1); }
        if (hn) { pack_store(0, nb); load_stage(tn, 1); }
#pragma unroll
        for (int kk = 3; kk < 7; kk++) { ldsm_all(kk + 1, (kk + 1) & 1); mma_all(kk & 1); }
        if (hn) { pack_store(1, nb); load_stage(tn, 2); }
#pragma unroll
        for (int kk = 7; kk < 11; kk++) { ldsm_all(kk + 1, (kk + 1) & 1); mma_all(kk & 1); }
        if (hn) { pack_store(2, nb); load_stage(tn, 3); }
#pragma unroll
        for (int kk = 11; kk < 15; kk++) { ldsm_all(kk + 1, (kk + 1) & 1); mma_all(kk & 1); }
        if (hn) { pack_store(3, nb); load_stage(tn, 4); }
#pragma unroll
        for (int kk = 15; kk < 17; kk++) { ldsm_all(kk + 1, (kk + 1) & 1); mma_all(kk & 1); }
        mma_all(17 & 1);
        if (hn) pack_store(4, nb);

        // ---- epilogue: bias + ReLU + pool, shfl-reduce over pixel rows
        float bv[16];
#pragma unroll
        for (int nt = 0; nt < 8; nt++)
#pragma unroll
            for (int c = 0; c < 2; c++)
                bv[nt * 2 + c] = sbias[nt * 8 + (lane & 3) * 2 + c];

        float ps[16];
#pragma unroll
        for (int i = 0; i < 16; i++) ps[i] = 0.0f;
#pragma unroll
        for (int mt = 0; mt < 4; mt++)
#pragma unroll
            for (int nt = 0; nt < 8; nt++)
#pragma unroll
                for (int h = 0; h < 2; h++) {
                    ps[nt * 2 + 0] += fmaxf(acc[mt][nt][2 * h + 0] + bv[nt * 2 + 0], 0.0f);
                    ps[nt * 2 + 1] += fmaxf(acc[mt][nt][2 * h + 1] + bv[nt * 2 + 1], 0.0f);
                }
#pragma unroll
        for (int off = 4; off < 32; off <<= 1)
#pragma unroll
            for (int i = 0; i < 16; i++)
                ps[i] += __shfl_xor_sync(0xFFFFFFFFu, ps[i], off);

        if (lane < 4) {
#pragma unroll
            for (int nt = 0; nt < 8; nt++) {
                spool[wm * 64 + nt * 8 + lane * 2 + 0] = ps[nt * 2 + 0];
                spool[wm * 64 + nt * 8 + lane * 2 + 1] = ps[nt * 2 + 1];
            }
        }
        __syncthreads();

        if (tid < OCN) {
            float s = 0.0f;
#pragma unroll
            for (int w = 0; w < 8; w++) s += spool[w * 64 + tid];
            g_partial[(size_t)t * OCN + tid] = s;
        }
        __syncthreads();   // spool consumed + next staging buffer published
    }
}

// ---------------------------------------------------------------- graph MLP
// 512 threads = two independent 256-thread groups, each one batch element.
__global__ __launch_bounds__(512, 1)
void mlp_kernel(const float* __restrict__ ew1, const float* __restrict__ eb1,
                const float* __restrict__ ew2, const float* __restrict__ eb2,
                const float* __restrict__ ow1, const float* __restrict__ ob1,
                const float* __restrict__ ow2, const float* __restrict__ ob2,
                float* __restrict__ out) {
    extern __shared__ float s[];
    float* sw1  = s;              // 128*64 = 8192
    float* sw2  = sw1 + 8192;     // 4096
    float* so1  = sw2 + 4096;     // 4096
    float* so2  = so1 + 4096;     // 64
    float* sb1  = so2 + 64;
    float* sb2  = sb1 + 64;
    float* sb3  = sb2 + 64;
    float* act  = sb3 + 64;       // 2 groups * 3328 floats

    const int tid   = threadIdx.x;
    const int grp   = tid >> 8;         // 0/1
    const int gtid  = tid & 255;
    const int p     = gtid >> 6;
    const int h     = gtid & 63;
    const int b     = blockIdx.x * 2 + grp;

    float* node = act + grp * 3328;     // 256
    float* us   = node + 256;           // 256
    float* vs   = us + 256;             // 256
    float* h1s  = vs + 256;             // 1024
    float* h2s  = h1s + 1024;           // 1024
    float* msg  = h2s + 1024;           // 256
    float* o1s  = msg + 256;            // 256

    for (int i = tid; i < 8192; i += 512) sw1[i] = ew1[i];
    for (int i = tid; i < 4096; i += 512) sw2[i] = ew2[i];
    for (int i = tid; i < 4096; i += 512) so1[i] = ow1[i];
    if (tid < 64) {
        so2[tid] = ow2[tid];
        sb1[tid] = eb1[tid];
        sb2[tid] = eb2[tid];
        sb3[tid] = ob1[tid];
    }

    // nodes[p][h] = mean over 8 tile partials / 4096
    {
        const float* gp = &g_partial[(size_t)((p * BB + b) * 8) * OCN + h];
        float sum = 0.0f;
#pragma unroll
        for (int k = 0; k < 8; k++) sum += gp[k * OCN];
        node[p * 64 + h] = sum * (1.0f / 4096.0f);
    }
    __syncthreads();

    // u/v factorization of edge layer 1: h1[(i,j)] = relu(u_i + v_j + b1)
    {
        float uu = 0.0f, vv = 0.0f;
        for (int k = 0; k < 64; k++) {
            float nk = node[p * 64 + k];
            uu = fmaf(nk, sw1[k * 64 + h], uu);
            vv = fmaf(nk, sw1[(64 + k) * 64 + h], vv);
        }
        us[p * 64 + h] = uu;
        vs[p * 64 + h] = vv;
    }
    __syncthreads();

#pragma unroll
    for (int e4 = 0; e4 < 4; e4++)
        h1s[(e4 * 4 + p) * 64 + h] =
            fmaxf(us[e4 * 64 + h] + vs[p * 64 + h] + sb1[h], 0.0f);
    __syncthreads();

    // h2[e] = relu(b2 + h1[e] . W2)
    {
        float acc[4];
#pragma unroll
        for (int e4 = 0; e4 < 4; e4++) acc[e4] = sb2[h];
        for (int k = 0; k < 64; k++) {
            float w = sw2[k * 64 + h];
#pragma unroll
            for (int e4 = 0; e4 < 4; e4++)
                acc[e4] = fmaf(h1s[(e4 * 4 + p) * 64 + k], w, acc[e4]);
        }
#pragma unroll
        for (int e4 = 0; e4 < 4; e4++)
            h2s[(e4 * 4 + p) * 64 + h] = fmaxf(acc[e4], 0.0f);
    }
    __syncthreads();

    {
        float m = 0.25f * (h2s[(0 * 4 + p) * 64 + h] + h2s[(1 * 4 + p) * 64 + h] +
                           h2s[(2 * 4 + p) * 64 + h] + h2s[(3 * 4 + p) * 64 + h]);
        msg[p * 64 + h] = m;
    }
    __syncthreads();
    {
        float s3 = sb3[h];
        for (int k = 0; k < 64; k++)
            s3 = fmaf(msg[p * 64 + k], so1[k * 64 + h], s3);
        o1s[p * 64 + h] = fmaxf(s3, 0.0f);
    }
    __syncthreads();

    if (gtid < PP) {
        float s4 = __ldg(&ob2[0]);
        for (int k = 0; k < 64; k++)
            s4 = fmaf(o1s[gtid * 64 + k], so2[k], s4);
        out[b * PP + gtid] = s4;
    }
}

// ---------------------------------------------------------------- launch
extern "C" void kernel_launch(void* const* d_in, const int* in_sizes, int n_in,
                              void* d_out, int out_size) {
    const float* x      = (const float*)d_in[0];
    const float* conv_w = (const float*)d_in[1];
    const float* conv_b = (const float*)d_in[2];
    const float* e_w1   = (const float*)d_in[3];
    const float* e_b1   = (const float*)d_in[4];
    const float* e_w2   = (const float*)d_in[5];
    const float* e_b2   = (const float*)d_in[6];
    const float* o_w1   = (const float*)d_in[7];
    const float* o_b1   = (const float*)d_in[8];
    const float* o_w2   = (const float*)d_in[9];
    const float* o_b2   = (const float*)d_in[10];
    float* out = (float*)d_out;

    cudaFuncSetAttribute(conv_mma_kernel,
                         cudaFuncAttributeMaxDynamicSharedMemorySize, SMEM_BYTES);
    const int smemB = (8192 + 4096 + 4096 + 64 * 4 + 2 * 3328) * (int)sizeof(float);
    cudaFuncSetAttribute(mlp_kernel,
                         cudaFuncAttributeMaxDynamicSharedMemorySize, smemB);

    conv_mma_kernel<<<GRIDC, 256, SMEM_BYTES>>>(x, conv_w, conv_b);
    mlp_kernel<<<BB / 2, 512, smemB>>>(e_w1, e_b1, e_w2, e_b2,
                                       o_w1, o_b1, o_w2, o_b2, out);
}